// round 2
// baseline (speedup 1.0000x reference)
#include <cuda_runtime.h>
#include <math.h>

#define THREADS 128
#define BM 64
#define BN 64
#define DH 64
#define TM 8
#define TN 4

// XOR swizzle on float4 granularity: row r, float4-col c4 (0..15).
// Rows are accessed at stride 4 in the S-gemm (r = tx*4+j), so swizzle key is r>>2.
__device__ __forceinline__ int swz(int r, int c4) {
    return (r << 4) + (c4 ^ ((r >> 2) & 15));
}

__global__ __launch_bounds__(THREADS, 3)
void gat_fp32_kernel(const float* __restrict__ Q, const float* __restrict__ K,
                     const float* __restrict__ V, const int* __restrict__ adj,
                     float* __restrict__ out, int N)
{
    extern __shared__ float4 sm4[];
    float4* Qs = sm4;                 // BM x 16 float4
    float4* Ks = Qs + BM * (DH / 4);  // BN x 16
    float4* Vs = Ks + BN * (DH / 4);  // BN x 16
    float4* Ps = Vs + BN * (DH / 4);  // BM x 16

    const int bh   = blockIdx.y;
    const int row0 = blockIdx.x * BM;

    const float4* Qb = reinterpret_cast<const float4*>(Q) + (size_t)bh * N * (DH / 4);
    const float4* Kb = reinterpret_cast<const float4*>(K) + (size_t)bh * N * (DH / 4);
    const float4* Vb = reinterpret_cast<const float4*>(V) + (size_t)bh * N * (DH / 4);

    const int tid = threadIdx.x;
    const int ty  = tid >> 4;   // 0..7  -> rows ty*8 .. ty*8+7
    const int tx  = tid & 15;   // 0..15 -> key-cols / d-cols tx*4 .. tx*4+3

    // ---- load Q tile (coalesced, swizzled store) ----
    #pragma unroll
    for (int i = tid; i < BM * DH / 4; i += THREADS) {
        int r = i >> 4, c4 = i & 15;
        Qs[swz(r, c4)] = Qb[(size_t)(row0 + r) * (DH / 4) + c4];
    }

    float acc[TM][TN];
    float m_i[TM], l_i[TM];
    #pragma unroll
    for (int i = 0; i < TM; i++) {
        m_i[i] = -INFINITY;
        l_i[i] = 0.0f;
        #pragma unroll
        for (int j = 0; j < TN; j++) acc[i][j] = 0.0f;
    }

    const int nTiles = N / BN;
    for (int t = 0; t < nTiles; t++) {
        const int col0 = t * BN;

        __syncthreads();  // protect Ks/Vs/Ps from previous iteration's readers
        #pragma unroll
        for (int i = tid; i < BN * DH / 4; i += THREADS) {
            int r = i >> 4, c4 = i & 15;
            Ks[swz(r, c4)] = Kb[(size_t)(col0 + r) * (DH / 4) + c4];
            Vs[swz(r, c4)] = Vb[(size_t)(col0 + r) * (DH / 4) + c4];
        }
        __syncthreads();

        // ---- S = Q K^T (8x4 fragment per thread) ----
        float s[TM][TN];
        #pragma unroll
        for (int i = 0; i < TM; i++)
            #pragma unroll
            for (int j = 0; j < TN; j++) s[i][j] = 0.0f;

        #pragma unroll
        for (int k4 = 0; k4 < DH / 4; k4++) {
            float4 kv[TN];
            #pragma unroll
            for (int j = 0; j < TN; j++) kv[j] = Ks[swz(tx * TN + j, k4)];
            #pragma unroll
            for (int i = 0; i < TM; i++) {
                float4 qv = Qs[swz(ty * TM + i, k4)];
                #pragma unroll
                for (int j = 0; j < TN; j++) {
                    s[i][j] = fmaf(qv.x, kv[j].x, s[i][j]);
                    s[i][j] = fmaf(qv.y, kv[j].y, s[i][j]);
                    s[i][j] = fmaf(qv.z, kv[j].z, s[i][j]);
                    s[i][j] = fmaf(qv.w, kv[j].w, s[i][j]);
                }
            }
        }

        // ---- mask + scale + online softmax update ----
        #pragma unroll
        for (int i = 0; i < TM; i++) {
            const int row = row0 + ty * TM + i;
            const int4 a = *reinterpret_cast<const int4*>(
                adj + (size_t)row * N + col0 + tx * TN);
            s[i][0] = (a.x > 0) ? s[i][0] * 0.125f : -9e15f;
            s[i][1] = (a.y > 0) ? s[i][1] * 0.125f : -9e15f;
            s[i][2] = (a.z > 0) ? s[i][2] * 0.125f : -9e15f;
            s[i][3] = (a.w > 0) ? s[i][3] * 0.125f : -9e15f;

            float tmax = fmaxf(fmaxf(s[i][0], s[i][1]), fmaxf(s[i][2], s[i][3]));
            #pragma unroll
            for (int o = 8; o >= 1; o >>= 1)
                tmax = fmaxf(tmax, __shfl_xor_sync(0xffffffffu, tmax, o));

            const float nm = fmaxf(m_i[i], tmax);
            const float f  = __expf(m_i[i] - nm);
            m_i[i] = nm;

            float p0 = __expf(s[i][0] - nm);
            float p1 = __expf(s[i][1] - nm);
            float p2 = __expf(s[i][2] - nm);
            float p3 = __expf(s[i][3] - nm);
            float sum = (p0 + p1) + (p2 + p3);
            #pragma unroll
            for (int o = 8; o >= 1; o >>= 1)
                sum += __shfl_xor_sync(0xffffffffu, sum, o);

            l_i[i] = l_i[i] * f + sum;
            #pragma unroll
            for (int j = 0; j < TN; j++) acc[i][j] *= f;

            Ps[swz(ty * TM + i, tx)] = make_float4(p0, p1, p2, p3);
        }
        __syncthreads();

        // ---- acc += P @ V  (8 rows x 4 d-cols per thread) ----
        #pragma unroll
        for (int c4 = 0; c4 < BN / 4; c4++) {
            float4 vv[4];
            #pragma unroll
            for (int cc = 0; cc < 4; cc++) vv[cc] = Vs[swz(c4 * 4 + cc, tx)];
            #pragma unroll
            for (int i = 0; i < TM; i++) {
                float4 p4 = Ps[swz(ty * TM + i, c4)];
                acc[i][0] = fmaf(p4.x, vv[0].x, acc[i][0]);
                acc[i][0] = fmaf(p4.y, vv[1].x, acc[i][0]);
                acc[i][0] = fmaf(p4.z, vv[2].x, acc[i][0]);
                acc[i][0] = fmaf(p4.w, vv[3].x, acc[i][0]);
                acc[i][1] = fmaf(p4.x, vv[0].y, acc[i][1]);
                acc[i][1] = fmaf(p4.y, vv[1].y, acc[i][1]);
                acc[i][1] = fmaf(p4.z, vv[2].y, acc[i][1]);
                acc[i][1] = fmaf(p4.w, vv[3].y, acc[i][1]);
                acc[i][2] = fmaf(p4.x, vv[0].z, acc[i][2]);
                acc[i][2] = fmaf(p4.y, vv[1].z, acc[i][2]);
                acc[i][2] = fmaf(p4.z, vv[2].z, acc[i][2]);
                acc[i][2] = fmaf(p4.w, vv[3].z, acc[i][2]);
                acc[i][3] = fmaf(p4.x, vv[0].w, acc[i][3]);
                acc[i][3] = fmaf(p4.y, vv[1].w, acc[i][3]);
                acc[i][3] = fmaf(p4.z, vv[2].w, acc[i][3]);
                acc[i][3] = fmaf(p4.w, vv[3].w, acc[i][3]);
            }
        }
    }

    // ---- epilogue: normalize and store [B,H,N,D] contiguous (== reshape(N,B,H,D)) ----
    #pragma unroll
    for (int i = 0; i < TM; i++) {
        const float inv = 1.0f / l_i[i];
        const int row = row0 + ty * TM + i;
        float4 o = make_float4(acc[i][0] * inv, acc[i][1] * inv,
                               acc[i][2] * inv, acc[i][3] * inv);
        reinterpret_cast<float4*>(out)[((size_t)bh * N + row) * (DH / 4) + tx] = o;
    }
}

extern "C" void kernel_launch(void* const* d_in, const int* in_sizes, int n_in,
                              void* d_out, int out_size)
{
    const float* Q   = (const float*)d_in[0];
    const float* K   = (const float*)d_in[1];
    const float* V   = (const float*)d_in[2];
    const int*   adj = (const int*)d_in[3];
    float*       out = (float*)d_out;

    // N from adj element count (N*N); BH from Q element count (BH*N*D)
    const int N  = (int)(sqrt((double)in_sizes[3]) + 0.5);
    const int BH = in_sizes[0] / (N * DH);

    const size_t smem_bytes = 4u * 64u * 16u * sizeof(float4);  // 64 KB
    cudaFuncSetAttribute(gat_fp32_kernel,
                         cudaFuncAttributeMaxDynamicSharedMemorySize,
                         (int)smem_bytes);

    dim3 grid(N / BM, BH);
    gat_fp32_kernel<<<grid, THREADS, smem_bytes>>>(Q, K, V, adj, out, N);
}

// round 3
// speedup vs baseline: 1.0012x; 1.0012x over previous
#include <cuda_runtime.h>
#include <math.h>

#define THREADS 128
#define BM 64
#define BN 64
#define DH 64
#define TM 8
#define TN 4

// XOR swizzle on float4 granularity: row r, float4-col c4 (0..15).
// Rows are accessed at stride 4 in the S-gemm (r = tx*4+j), so swizzle key is r>>2.
__device__ __forceinline__ int swz(int r, int c4) {
    return (r << 4) + (c4 ^ ((r >> 2) & 15));
}

__global__ __launch_bounds__(THREADS, 3)
void gat_fp32_kernel(const float* __restrict__ Q, const float* __restrict__ K,
                     const float* __restrict__ V, const int* __restrict__ adj,
                     float* __restrict__ out, int N)
{
    extern __shared__ float4 sm4[];
    float4* Qs = sm4;                 // BM x 16 float4
    float4* Ks = Qs + BM * (DH / 4);  // BN x 16
    float4* Vs = Ks + BN * (DH / 4);  // BN x 16
    float4* Ps = Vs + BN * (DH / 4);  // BM x 16

    const int bh   = blockIdx.y;
    const int row0 = blockIdx.x * BM;

    const float4* Qb = reinterpret_cast<const float4*>(Q) + (size_t)bh * N * (DH / 4);
    const float4* Kb = reinterpret_cast<const float4*>(K) + (size_t)bh * N * (DH / 4);
    const float4* Vb = reinterpret_cast<const float4*>(V) + (size_t)bh * N * (DH / 4);

    const int tid = threadIdx.x;
    const int ty  = tid >> 4;   // 0..7  -> rows ty*8 .. ty*8+7
    const int tx  = tid & 15;   // 0..15 -> key-cols / d-cols tx*4 .. tx*4+3

    // ---- load Q tile (coalesced, swizzled store) ----
    #pragma unroll
    for (int i = tid; i < BM * DH / 4; i += THREADS) {
        int r = i >> 4, c4 = i & 15;
        Qs[swz(r, c4)] = Qb[(size_t)(row0 + r) * (DH / 4) + c4];
    }

    float acc[TM][TN];
    float m_i[TM], l_i[TM];
    #pragma unroll
    for (int i = 0; i < TM; i++) {
        m_i[i] = -INFINITY;
        l_i[i] = 0.0f;
        #pragma unroll
        for (int j = 0; j < TN; j++) acc[i][j] = 0.0f;
    }

    const int nTiles = N / BN;
    for (int t = 0; t < nTiles; t++) {
        const int col0 = t * BN;

        __syncthreads();  // protect Ks/Vs/Ps from previous iteration's readers
        #pragma unroll
        for (int i = tid; i < BN * DH / 4; i += THREADS) {
            int r = i >> 4, c4 = i & 15;
            Ks[swz(r, c4)] = Kb[(size_t)(col0 + r) * (DH / 4) + c4];
            Vs[swz(r, c4)] = Vb[(size_t)(col0 + r) * (DH / 4) + c4];
        }
        __syncthreads();

        // ---- S = Q K^T (8x4 fragment per thread) ----
        float s[TM][TN];
        #pragma unroll
        for (int i = 0; i < TM; i++)
            #pragma unroll
            for (int j = 0; j < TN; j++) s[i][j] = 0.0f;

        #pragma unroll
        for (int k4 = 0; k4 < DH / 4; k4++) {
            float4 kv[TN];
            #pragma unroll
            for (int j = 0; j < TN; j++) kv[j] = Ks[swz(tx * TN + j, k4)];
            #pragma unroll
            for (int i = 0; i < TM; i++) {
                float4 qv = Qs[swz(ty * TM + i, k4)];
                #pragma unroll
                for (int j = 0; j < TN; j++) {
                    s[i][j] = fmaf(qv.x, kv[j].x, s[i][j]);
                    s[i][j] = fmaf(qv.y, kv[j].y, s[i][j]);
                    s[i][j] = fmaf(qv.z, kv[j].z, s[i][j]);
                    s[i][j] = fmaf(qv.w, kv[j].w, s[i][j]);
                }
            }
        }

        // ---- mask + scale + online softmax update ----
        #pragma unroll
        for (int i = 0; i < TM; i++) {
            const int row = row0 + ty * TM + i;
            const int4 a = *reinterpret_cast<const int4*>(
                adj + (size_t)row * N + col0 + tx * TN);
            s[i][0] = (a.x > 0) ? s[i][0] * 0.125f : -9e15f;
            s[i][1] = (a.y > 0) ? s[i][1] * 0.125f : -9e15f;
            s[i][2] = (a.z > 0) ? s[i][2] * 0.125f : -9e15f;
            s[i][3] = (a.w > 0) ? s[i][3] * 0.125f : -9e15f;

            float tmax = fmaxf(fmaxf(s[i][0], s[i][1]), fmaxf(s[i][2], s[i][3]));
            #pragma unroll
            for (int o = 8; o >= 1; o >>= 1)
                tmax = fmaxf(tmax, __shfl_xor_sync(0xffffffffu, tmax, o));

            const float nm = fmaxf(m_i[i], tmax);
            const float f  = __expf(m_i[i] - nm);
            m_i[i] = nm;

            float p0 = __expf(s[i][0] - nm);
            float p1 = __expf(s[i][1] - nm);
            float p2 = __expf(s[i][2] - nm);
            float p3 = __expf(s[i][3] - nm);
            float sum = (p0 + p1) + (p2 + p3);
            #pragma unroll
            for (int o = 8; o >= 1; o >>= 1)
                sum += __shfl_xor_sync(0xffffffffu, sum, o);

            l_i[i] = l_i[i] * f + sum;
            #pragma unroll
            for (int j = 0; j < TN; j++) acc[i][j] *= f;

            Ps[swz(ty * TM + i, tx)] = make_float4(p0, p1, p2, p3);
        }
        __syncthreads();

        // ---- acc += P @ V  (8 rows x 4 d-cols per thread) ----
        #pragma unroll
        for (int c4 = 0; c4 < BN / 4; c4++) {
            float4 vv[4];
            #pragma unroll
            for (int cc = 0; cc < 4; cc++) vv[cc] = Vs[swz(c4 * 4 + cc, tx)];
            #pragma unroll
            for (int i = 0; i < TM; i++) {
                float4 p4 = Ps[swz(ty * TM + i, c4)];
                acc[i][0] = fmaf(p4.x, vv[0].x, acc[i][0]);
                acc[i][0] = fmaf(p4.y, vv[1].x, acc[i][0]);
                acc[i][0] = fmaf(p4.z, vv[2].x, acc[i][0]);
                acc[i][0] = fmaf(p4.w, vv[3].x, acc[i][0]);
                acc[i][1] = fmaf(p4.x, vv[0].y, acc[i][1]);
                acc[i][1] = fmaf(p4.y, vv[1].y, acc[i][1]);
                acc[i][1] = fmaf(p4.z, vv[2].y, acc[i][1]);
                acc[i][1] = fmaf(p4.w, vv[3].y, acc[i][1]);
                acc[i][2] = fmaf(p4.x, vv[0].z, acc[i][2]);
                acc[i][2] = fmaf(p4.y, vv[1].z, acc[i][2]);
                acc[i][2] = fmaf(p4.z, vv[2].z, acc[i][2]);
                acc[i][2] = fmaf(p4.w, vv[3].z, acc[i][2]);
                acc[i][3] = fmaf(p4.x, vv[0].w, acc[i][3]);
                acc[i][3] = fmaf(p4.y, vv[1].w, acc[i][3]);
                acc[i][3] = fmaf(p4.z, vv[2].w, acc[i][3]);
                acc[i][3] = fmaf(p4.w, vv[3].w, acc[i][3]);
            }
        }
    }

    // ---- epilogue: normalize and store [B,H,N,D] contiguous (== reshape(N,B,H,D)) ----
    #pragma unroll
    for (int i = 0; i < TM; i++) {
        const float inv = 1.0f / l_i[i];
        const int row = row0 + ty * TM + i;
        float4 o = make_float4(acc[i][0] * inv, acc[i][1] * inv,
                               acc[i][2] * inv, acc[i][3] * inv);
        reinterpret_cast<float4*>(out)[((size_t)bh * N + row) * (DH / 4) + tx] = o;
    }
}

extern "C" void kernel_launch(void* const* d_in, const int* in_sizes, int n_in,
                              void* d_out, int out_size)
{
    const float* Q   = (const float*)d_in[0];
    const float* K   = (const float*)d_in[1];
    const float* V   = (const float*)d_in[2];
    const int*   adj = (const int*)d_in[3];
    float*       out = (float*)d_out;

    // N from adj element count (N*N); BH from Q element count (BH*N*D)
    const int N  = (int)(sqrt((double)in_sizes[3]) + 0.5);
    const int BH = in_sizes[0] / (N * DH);

    const size_t smem_bytes = 4u * 64u * 16u * sizeof(float4);  // 64 KB
    cudaFuncSetAttribute(gat_fp32_kernel,
                         cudaFuncAttributeMaxDynamicSharedMemorySize,
                         (int)smem_bytes);

    dim3 grid(N / BM, BH);
    gat_fp32_kernel<<<grid, THREADS, smem_bytes>>>(Q, K, V, adj, out, N);
}

// round 5
// speedup vs baseline: 3.5062x; 3.5020x over previous
#include <cuda_runtime.h>
#include <cuda_fp16.h>
#include <math.h>
#include <stdint.h>

#define TPB 128
#define BM  64
#define BN  64
#define DHD 64
#define RS  72          // halves per smem row (padded)
#define RB  144         // bytes per smem row

// smem byte offsets
#define OFF_QH 0
#define OFF_QL 9216
#define OFF_KH 18432
#define OFF_KL 27648
#define OFF_VH 36864
#define OFF_VL 46080
#define OFF_SB 55296    // 64 floats: per-row bias (14 - M*log2e)
#define SMEM_TOTAL 55552

#define K2E 0.1803368801f   // log2(e)/8

__device__ uint32_t g_adjbits[2048 * 2048 / 32];
__device__ float    g_maxk[64];

// ---------------- helpers ----------------
__device__ __forceinline__ uint32_t smem_u32(const void* p) {
    uint32_t a;
    asm("{ .reg .u64 t; cvta.to.shared.u64 t, %1; cvt.u32.u64 %0, t; }" : "=r"(a) : "l"(p));
    return a;
}
__device__ __forceinline__ void ldsm_x4(uint32_t* r, uint32_t a) {
    asm volatile("ldmatrix.sync.aligned.m8n8.x4.shared.b16 {%0,%1,%2,%3}, [%4];"
                 : "=r"(r[0]), "=r"(r[1]), "=r"(r[2]), "=r"(r[3]) : "r"(a));
}
__device__ __forceinline__ void ldsm_x4t(uint32_t* r, uint32_t a) {
    asm volatile("ldmatrix.sync.aligned.m8n8.x4.trans.shared.b16 {%0,%1,%2,%3}, [%4];"
                 : "=r"(r[0]), "=r"(r[1]), "=r"(r[2]), "=r"(r[3]) : "r"(a));
}
__device__ __forceinline__ void mma16816(float* c, const uint32_t* a, uint32_t b0, uint32_t b1) {
    asm volatile("mma.sync.aligned.m16n8k16.row.col.f32.f16.f16.f32 "
                 "{%0,%1,%2,%3}, {%4,%5,%6,%7}, {%8,%9}, {%0,%1,%2,%3};"
                 : "+f"(c[0]), "+f"(c[1]), "+f"(c[2]), "+f"(c[3])
                 : "r"(a[0]), "r"(a[1]), "r"(a[2]), "r"(a[3]), "r"(b0), "r"(b1));
}
__device__ __forceinline__ float ex2(float x) {
    float r; asm("ex2.approx.f32 %0, %1;" : "=f"(r) : "f"(x)); return r;
}
__device__ __forceinline__ uint32_t h2bits(__half2 h) { return *(uint32_t*)&h; }

// fp32x4 -> fp16 hi/lo split, store 8B each
__device__ __forceinline__ void cvt_store(char* hi, char* lo, int off, float4 v) {
    __half2 h0 = __floats2half2_rn(v.x, v.y);
    __half2 h1 = __floats2half2_rn(v.z, v.w);
    float2 f0 = __half22float2(h0), f1 = __half22float2(h1);
    __half2 l0 = __floats2half2_rn(v.x - f0.x, v.y - f0.y);
    __half2 l1 = __floats2half2_rn(v.z - f1.x, v.w - f1.y);
    *(uint2*)(hi + off) = make_uint2(h2bits(h0), h2bits(h1));
    *(uint2*)(lo + off) = make_uint2(h2bits(l0), h2bits(l1));
}

// ---------------- prepass kernels ----------------
__global__ void pack_adj_kernel(const int* __restrict__ adj) {
    int i = blockIdx.x * 256 + threadIdx.x;
    uint32_t b = __ballot_sync(0xffffffffu, adj[i] > 0);
    if ((threadIdx.x & 31) == 0) g_adjbits[i >> 5] = b;
}

__global__ void maxk_kernel(const float* __restrict__ K, int N) {
    __shared__ float wm[16];
    int bh = blockIdx.x;
    int wid = threadIdx.x >> 5, lane = threadIdx.x & 31;
    const float2* Kb = (const float2*)K + (size_t)bh * N * (DHD / 2);
    float m = 0.f;
    for (int r = wid; r < N; r += 16) {
        float2 v = Kb[r * (DHD / 2) + lane];
        float s = v.x * v.x + v.y * v.y;
        #pragma unroll
        for (int o = 16; o; o >>= 1) s += __shfl_xor_sync(0xffffffffu, s, o);
        m = fmaxf(m, s);
    }
    if (lane == 0) wm[wid] = m;
    __syncthreads();
    if (threadIdx.x == 0) {
        float mm = 0.f;
        #pragma unroll
        for (int i = 0; i < 16; i++) mm = fmaxf(mm, wm[i]);
        g_maxk[bh] = sqrtf(mm);
    }
}

// ---------------- main kernel ----------------
__global__ __launch_bounds__(TPB, 3)
void gat_hmma_kernel(const float* __restrict__ Q, const float* __restrict__ K,
                     const float* __restrict__ V, float* __restrict__ out, int N)
{
    extern __shared__ char sm[];
    const uint32_t smb = smem_u32(sm);
    float* sB = (float*)(sm + OFF_SB);

    const int tid  = threadIdx.x;
    const int wid  = tid >> 5;
    const int lane = tid & 31;
    const int mg   = lane >> 3;   // ldmatrix address group 0..3
    const int mr   = lane & 7;
    const int r4   = lane >> 2;   // fragment row within 8
    const int qd   = lane & 3;    // fragment col quad

    const int bh   = blockIdx.y;
    const int row0 = blockIdx.x * BM;
    const int nT   = N / BN;
    const int adjw = N >> 5;

    const float4* Qb  = (const float4*)Q + ((size_t)bh * N + row0) * (DHD / 4);
    const float4* Kbh = (const float4*)K + (size_t)bh * N * (DHD / 4);
    const float4* Vbh = (const float4*)V + (size_t)bh * N * (DHD / 4);

    // ---- Q convert + per-row bias ----
    const float mk = g_maxk[bh];
    #pragma unroll
    for (int i = 0; i < 8; i++) {
        int idx = tid + i * TPB;
        int r = idx >> 4, c4 = idx & 15;
        float4 q = Qb[idx];
        cvt_store(sm + OFF_QH, sm + OFF_QL, r * RB + c4 * 8, q);
        float n2 = q.x * q.x + q.y * q.y + q.z * q.z + q.w * q.w;
        #pragma unroll
        for (int o = 8; o; o >>= 1) n2 += __shfl_xor_sync(0xffffffffu, n2, o);
        if ((tid & 15) == 0) sB[r] = 14.0f - sqrtf(n2) * mk * K2E;
    }
    __syncthreads();

    const float sb0 = sB[wid * 16 + r4];
    const float sb1 = sB[wid * 16 + 8 + r4];
    const uint32_t* ab0 = g_adjbits + (size_t)(row0 + wid * 16 + r4) * adjw;
    const uint32_t* ab1 = ab0 + (size_t)8 * adjw;

    float o[8][4];
    #pragma unroll
    for (int i = 0; i < 8; i++)
        #pragma unroll
        for (int j = 0; j < 4; j++) o[i][j] = 0.f;
    float l0 = 0.f, l1 = 0.f;

    for (int t = 0; t < nT; t++) {
        __syncthreads();   // previous tile's V reads complete
        const float4* Kt = Kbh + (size_t)t * BN * (DHD / 4);
        const float4* Vt = Vbh + (size_t)t * BN * (DHD / 4);
        #pragma unroll
        for (int i = 0; i < 8; i++) {
            int idx = tid + i * TPB;
            int off = (idx >> 4) * RB + (idx & 15) * 8;
            cvt_store(sm + OFF_KH, sm + OFF_KL, off, Kt[idx]);
            cvt_store(sm + OFF_VH, sm + OFF_VL, off, Vt[idx]);
        }
        __syncthreads();

        // ---- S = Qh*Kh + Qh*Kl + Ql*Kh ----
        float c[8][4];
        #pragma unroll
        for (int i = 0; i < 8; i++)
            #pragma unroll
            for (int j = 0; j < 4; j++) c[i][j] = 0.f;

        #pragma unroll
        for (int kb = 0; kb < 4; kb++) {
            const int aoff = (wid * 16 + ((mg & 1) << 3) + mr) * RB + (kb * 16 + ((mg >> 1) << 3)) * 2;
            uint32_t ah[4], al[4];
            ldsm_x4(ah, smb + OFF_QH + aoff);
            ldsm_x4(al, smb + OFF_QL + aoff);
            #pragma unroll
            for (int j = 0; j < 4; j++) {
                const int boff = (j * 16 + ((mg >> 1) << 3) + mr) * RB + (kb * 16 + ((mg & 1) << 3)) * 2;
                uint32_t bhr[4], blr[4];
                ldsm_x4(bhr, smb + OFF_KH + boff);
                ldsm_x4(blr, smb + OFF_KL + boff);
                mma16816(c[2 * j],     ah, bhr[0], bhr[1]);
                mma16816(c[2 * j + 1], ah, bhr[2], bhr[3]);
                mma16816(c[2 * j],     ah, blr[0], blr[1]);
                mma16816(c[2 * j + 1], ah, blr[2], blr[3]);
                mma16816(c[2 * j],     al, bhr[0], bhr[1]);
                mma16816(c[2 * j + 1], al, bhr[2], bhr[3]);
            }
        }

        // ---- mask + scaled exp (p stored back into c) ----
        uint2 w0 = *(const uint2*)(ab0 + t * 2);
        uint2 w1 = *(const uint2*)(ab1 + t * 2);
        uint64_t m0 = (uint64_t)w0.x | ((uint64_t)w0.y << 32);
        uint64_t m1 = (uint64_t)w1.x | ((uint64_t)w1.y << 32);
        #pragma unroll
        for (int nb = 0; nb < 8; nb++) {
            const int cb = nb * 8 + qd * 2;
            #pragma unroll
            for (int qq = 0; qq < 2; qq++) {
                float tv = fmaf(c[nb][qq], K2E, sb0);
                float p = ((m0 >> (cb + qq)) & 1u) ? ex2(tv) : 0.f;
                l0 += p; c[nb][qq] = p;
                tv = fmaf(c[nb][2 + qq], K2E, sb1);
                p = ((m1 >> (cb + qq)) & 1u) ? ex2(tv) : 0.f;
                l1 += p; c[nb][2 + qq] = p;
            }
        }

        // ---- O += Ph*Vh + Ph*Vl + Pl*Vh (P from registers) ----
        #pragma unroll
        for (int kb2 = 0; kb2 < 4; kb2++) {
            const int e = 2 * kb2, od = e + 1;
            uint32_t ph[4], pl[4];
            {
                __half2 h; float2 f; __half2 lw;
                h = __floats2half2_rn(c[e][0], c[e][1]);  f = __half22float2(h);
                lw = __floats2half2_rn(c[e][0] - f.x, c[e][1] - f.y);
                ph[0] = h2bits(h); pl[0] = h2bits(lw);
                h = __floats2half2_rn(c[e][2], c[e][3]);  f = __half22float2(h);
                lw = __floats2half2_rn(c[e][2] - f.x, c[e][3] - f.y);
                ph[1] = h2bits(h); pl[1] = h2bits(lw);
                h = __floats2half2_rn(c[od][0], c[od][1]); f = __half22float2(h);
                lw = __floats2half2_rn(c[od][0] - f.x, c[od][1] - f.y);
                ph[2] = h2bits(h); pl[2] = h2bits(lw);
                h = __floats2half2_rn(c[od][2], c[od][3]); f = __half22float2(h);
                lw = __floats2half2_rn(c[od][2] - f.x, c[od][3] - f.y);
                ph[3] = h2bits(h); pl[3] = h2bits(lw);
            }
            #pragma unroll
            for (int j = 0; j < 4; j++) {
                const int voff = (kb2 * 16 + ((mg & 1) << 3) + mr) * RB + (j * 16 + ((mg >> 1) << 3)) * 2;
                uint32_t vh4[4], vl4[4];
                ldsm_x4t(vh4, smb + OFF_VH + voff);
                ldsm_x4t(vl4, smb + OFF_VL + voff);
                mma16816(o[2 * j],     ph, vh4[0], vh4[1]);
                mma16816(o[2 * j + 1], ph, vh4[2], vh4[3]);
                mma16816(o[2 * j],     ph, vl4[0], vl4[1]);
                mma16816(o[2 * j + 1], ph, vl4[2], vl4[3]);
                mma16816(o[2 * j],     pl, vh4[0], vh4[1]);
                mma16816(o[2 * j + 1], pl, vh4[2], vh4[3]);
            }
        }
    }

    // ---- normalize + store ----
    l0 += __shfl_xor_sync(0xffffffffu, l0, 1);
    l0 += __shfl_xor_sync(0xffffffffu, l0, 2);
    l1 += __shfl_xor_sync(0xffffffffu, l1, 1);
    l1 += __shfl_xor_sync(0xffffffffu, l1, 2);
    const float inv0 = 1.0f / l0;
    const float inv1 = 1.0f / l1;

    const int orow = row0 + wid * 16 + r4;
    float2* op = (float2*)out;
    #pragma unroll
    for (int nb = 0; nb < 8; nb++) {
        const int d = nb * 8 + qd * 2;
        op[(((size_t)bh * N + orow) * DHD + d) >> 1] =
            make_float2(o[nb][0] * inv0, o[nb][1] * inv0);
        op[(((size_t)bh * N + orow + 8) * DHD + d) >> 1] =
            make_float2(o[nb][2] * inv1, o[nb][3] * inv1);
    }
}

// ---------------- launcher ----------------
extern "C" void kernel_launch(void* const* d_in, const int* in_sizes, int n_in,
                              void* d_out, int out_size)
{
    const float* Q   = (const float*)d_in[0];
    const float* K   = (const float*)d_in[1];
    const float* V   = (const float*)d_in[2];
    const int*   adj = (const int*)d_in[3];
    float*       out = (float*)d_out;

    const int N  = (int)(sqrt((double)in_sizes[3]) + 0.5);
    const int BH = in_sizes[0] / (N * DHD);

    pack_adj_kernel<<<(N * N) / 256, 256>>>(adj);
    maxk_kernel<<<BH, 512>>>(K, N);

    cudaFuncSetAttribute(gat_hmma_kernel,
                         cudaFuncAttributeMaxDynamicSharedMemorySize, SMEM_TOTAL);
    dim3 grid(N / BM, BH);
    gat_hmma_kernel<<<grid, TPB, SMEM_TOTAL>>>(Q, K, V, out, N);
}

// round 6
// speedup vs baseline: 3.7629x; 1.0732x over previous
#include <cuda_runtime.h>
#include <cuda_fp16.h>
#include <math.h>
#include <stdint.h>

#define TPB 128
#define BM  64
#define BN  64
#define DHD 64
#define K2E 0.1803368801f   // log2(e)/8

// problem-shape constants (B=4,H=8,N=2048,D=64)
#define BH_MAX 32
#define N_MAX  2048
#define MAXE   (BH_MAX * N_MAX * DHD)

// stage layout (bytes): KH 0, KL 8192, VH 16384, VL 24576; stage stride 32768
#define STG 32768
#define SMEM_TOTAL (2 * STG)

__device__ __align__(16) __half g_qh[MAXE];
__device__ __align__(16) __half g_ql[MAXE];
__device__ __align__(16) __half g_kh[MAXE];
__device__ __align__(16) __half g_kl[MAXE];
__device__ __align__(16) __half g_vh[MAXE];
__device__ __align__(16) __half g_vl[MAXE];
__device__ float    g_qn2[BH_MAX * N_MAX];
__device__ float    g_maxk2[BH_MAX];
__device__ uint32_t g_adjbits[N_MAX * N_MAX / 32];

// ---------------- helpers ----------------
__device__ __forceinline__ uint32_t smem_u32(const void* p) {
    uint32_t a;
    asm("{ .reg .u64 t; cvta.to.shared.u64 t, %1; cvt.u32.u64 %0, t; }" : "=r"(a) : "l"(p));
    return a;
}
__device__ __forceinline__ void cp16(uint32_t dst, const void* src) {
    asm volatile("cp.async.cg.shared.global [%0], [%1], 16;" :: "r"(dst), "l"(src));
}
#define CP_COMMIT() asm volatile("cp.async.commit_group;" ::: "memory")
#define CP_WAIT0()  asm volatile("cp.async.wait_group 0;" ::: "memory")
#define CP_WAIT1()  asm volatile("cp.async.wait_group 1;" ::: "memory")

__device__ __forceinline__ void ldsm_x4(uint32_t* r, uint32_t a) {
    asm volatile("ldmatrix.sync.aligned.m8n8.x4.shared.b16 {%0,%1,%2,%3}, [%4];"
                 : "=r"(r[0]), "=r"(r[1]), "=r"(r[2]), "=r"(r[3]) : "r"(a));
}
__device__ __forceinline__ void ldsm_x4t(uint32_t* r, uint32_t a) {
    asm volatile("ldmatrix.sync.aligned.m8n8.x4.trans.shared.b16 {%0,%1,%2,%3}, [%4];"
                 : "=r"(r[0]), "=r"(r[1]), "=r"(r[2]), "=r"(r[3]) : "r"(a));
}
__device__ __forceinline__ void mma16816(float* c, const uint32_t* a, uint32_t b0, uint32_t b1) {
    asm volatile("mma.sync.aligned.m16n8k16.row.col.f32.f16.f16.f32 "
                 "{%0,%1,%2,%3}, {%4,%5,%6,%7}, {%8,%9}, {%0,%1,%2,%3};"
                 : "+f"(c[0]), "+f"(c[1]), "+f"(c[2]), "+f"(c[3])
                 : "r"(a[0]), "r"(a[1]), "r"(a[2]), "r"(a[3]), "r"(b0), "r"(b1));
}
__device__ __forceinline__ float ex2(float x) {
    float r; asm("ex2.approx.f32 %0, %1;" : "=f"(r) : "f"(x)); return r;
}
__device__ __forceinline__ uint32_t h2bits(__half2 h) { return *(uint32_t*)&h; }
// 128B-row XOR swizzle (conflict-free ldmatrix + cp.async dst)
__device__ __forceinline__ uint32_t swzo(int row, int colb) {
    return (uint32_t)((row * 128 + colb) ^ ((row & 7) << 4));
}

// ---------------- prepass: convert + norms ----------------
__global__ void cvt_prepass(const float4* __restrict__ Q, const float4* __restrict__ K,
                            const float4* __restrict__ V, int N)
{
    __shared__ float skn[16];
    const int idx = blockIdx.x * 256 + threadIdx.x;   // float4 index
    float4 q = Q[idx], k = K[idx], v = V[idx];

    // split & store (8B hi + 8B lo per float4)
    {
        __half2 h0, h1, l0, l1; float2 f0, f1;
        h0 = __floats2half2_rn(q.x, q.y); h1 = __floats2half2_rn(q.z, q.w);
        f0 = __half22float2(h0); f1 = __half22float2(h1);
        l0 = __floats2half2_rn(q.x - f0.x, q.y - f0.y);
        l1 = __floats2half2_rn(q.z - f1.x, q.w - f1.y);
        ((uint2*)g_qh)[idx] = make_uint2(h2bits(h0), h2bits(h1));
        ((uint2*)g_ql)[idx] = make_uint2(h2bits(l0), h2bits(l1));
        h0 = __floats2half2_rn(k.x, k.y); h1 = __floats2half2_rn(k.z, k.w);
        f0 = __half22float2(h0); f1 = __half22float2(h1);
        l0 = __floats2half2_rn(k.x - f0.x, k.y - f0.y);
        l1 = __floats2half2_rn(k.z - f1.x, k.w - f1.y);
        ((uint2*)g_kh)[idx] = make_uint2(h2bits(h0), h2bits(h1));
        ((uint2*)g_kl)[idx] = make_uint2(h2bits(l0), h2bits(l1));
        h0 = __floats2half2_rn(v.x, v.y); h1 = __floats2half2_rn(v.z, v.w);
        f0 = __half22float2(h0); f1 = __half22float2(h1);
        l0 = __floats2half2_rn(v.x - f0.x, v.y - f0.y);
        l1 = __floats2half2_rn(v.z - f1.x, v.w - f1.y);
        ((uint2*)g_vh)[idx] = make_uint2(h2bits(h0), h2bits(h1));
        ((uint2*)g_vl)[idx] = make_uint2(h2bits(l0), h2bits(l1));
    }

    float qn2 = q.x * q.x + q.y * q.y + q.z * q.z + q.w * q.w;
    float kn2 = k.x * k.x + k.y * k.y + k.z * k.z + k.w * k.w;
    #pragma unroll
    for (int o = 8; o; o >>= 1) {
        qn2 += __shfl_xor_sync(0xffffffffu, qn2, o);
        kn2 += __shfl_xor_sync(0xffffffffu, kn2, o);
    }
    if ((threadIdx.x & 15) == 0) {
        g_qn2[idx >> 4] = qn2;
        skn[threadIdx.x >> 4] = kn2;
    }
    __syncthreads();
    if (threadIdx.x == 0) {
        float m = skn[0];
        #pragma unroll
        for (int i = 1; i < 16; i++) m = fmaxf(m, skn[i]);
        int bh = (idx >> 4) / N;
        atomicMax((int*)&g_maxk2[bh], __float_as_int(m));
    }
}

// ---------------- prepass: adjacency bit-pack (int4 + shfl gather) ----------------
__global__ void pack_adj_kernel(const int4* __restrict__ adj) {
    const int g = blockIdx.x * 256 + threadIdx.x;   // int4 index
    int4 a = adj[g];
    uint32_t nib = (a.x > 0 ? 1u : 0u) | (a.y > 0 ? 2u : 0u)
                 | (a.z > 0 ? 4u : 0u) | (a.w > 0 ? 8u : 0u);
    uint32_t v = nib << (4 * (threadIdx.x & 7));
    v |= __shfl_xor_sync(0xffffffffu, v, 1);
    v |= __shfl_xor_sync(0xffffffffu, v, 2);
    v |= __shfl_xor_sync(0xffffffffu, v, 4);
    if ((threadIdx.x & 7) == 0) g_adjbits[g >> 3] = v;
}

// ---------------- main kernel ----------------
__global__ __launch_bounds__(TPB, 2)
void gat_hmma2_kernel(float* __restrict__ out, int N)
{
    extern __shared__ char sm[];
    const uint32_t smb = smem_u32(sm);

    const int tid  = threadIdx.x;
    const int wid  = tid >> 5;
    const int lane = tid & 31;
    const int mg   = lane >> 3;
    const int mr   = lane & 7;
    const int r4   = lane >> 2;
    const int qd   = lane & 3;

    const int bh   = blockIdx.y;
    const int row0 = blockIdx.x * BM;
    const int nT   = N / BN;
    const int adjw = N >> 5;

    // ---- Q fragments: stage QH/QL into buf0, ldmatrix to regs ----
    {
        const char* qhB = (const char*)g_qh + ((size_t)bh * N + row0) * (DHD * 2);
        const char* qlB = (const char*)g_ql + ((size_t)bh * N + row0) * (DHD * 2);
        #pragma unroll
        for (int i = 0; i < 4; i++) {
            int idx = tid + i * TPB;
            int row = idx >> 3, c = idx & 7;
            uint32_t so = swzo(row, c * 16);
            cp16(smb + so,        qhB + row * 128 + c * 16);
            cp16(smb + 8192 + so, qlB + row * 128 + c * 16);
        }
        CP_COMMIT(); CP_WAIT0();
        __syncthreads();
    }
    uint32_t qh[4][4], ql[4][4];
    {
        const int arow = wid * 16 + ((mg & 1) << 3) + mr;
        #pragma unroll
        for (int kb = 0; kb < 4; kb++) {
            const int acol = kb * 32 + ((mg >> 1) << 4);
            ldsm_x4(qh[kb], smb + swzo(arow, acol));
            ldsm_x4(ql[kb], smb + 8192 + swzo(arow, acol));
        }
    }
    __syncthreads();   // buf0 free for tile 0

    // ---- per-row bias + adjacency pointers ----
    const float mk2 = g_maxk2[bh];
    const float qn2a = g_qn2[(size_t)bh * N + row0 + wid * 16 + r4];
    const float qn2b = g_qn2[(size_t)bh * N + row0 + wid * 16 + 8 + r4];
    const float sb0 = 14.0f - sqrtf(qn2a * mk2) * K2E;
    const float sb1 = 14.0f - sqrtf(qn2b * mk2) * K2E;
    const uint32_t* ab0 = g_adjbits + (size_t)(row0 + wid * 16 + r4) * adjw;
    const uint32_t* ab1 = ab0 + (size_t)8 * adjw;

    const char* khB = (const char*)g_kh + (size_t)bh * N * (DHD * 2);
    const char* klB = (const char*)g_kl + (size_t)bh * N * (DHD * 2);
    const char* vhB = (const char*)g_vh + (size_t)bh * N * (DHD * 2);
    const char* vlB = (const char*)g_vl + (size_t)bh * N * (DHD * 2);

    float o[8][4];
    #pragma unroll
    for (int i = 0; i < 8; i++)
        #pragma unroll
        for (int j = 0; j < 4; j++) o[i][j] = 0.f;
    float l0 = 0.f, l1 = 0.f;

    // prefetch tile 0 into stage 0
    {
        #pragma unroll
        for (int i = 0; i < 4; i++) {
            int idx = tid + i * TPB;
            int row = idx >> 3, c = idx & 7;
            uint32_t so = swzo(row, c * 16);
            size_t go = (size_t)row * 128 + c * 16;
            cp16(smb + so,         khB + go);
            cp16(smb + 8192  + so, klB + go);
            cp16(smb + 16384 + so, vhB + go);
            cp16(smb + 24576 + so, vlB + go);
        }
        CP_COMMIT();
    }

    for (int t = 0; t < nT; t++) {
        if (t + 1 < nT) {
            const uint32_t sd = smb + ((t + 1) & 1) * STG;
            const size_t tb = (size_t)(t + 1) * BN * (DHD * 2);
            #pragma unroll
            for (int i = 0; i < 4; i++) {
                int idx = tid + i * TPB;
                int row = idx >> 3, c = idx & 7;
                uint32_t so = swzo(row, c * 16);
                size_t go = tb + (size_t)row * 128 + c * 16;
                cp16(sd + so,         khB + go);
                cp16(sd + 8192  + so, klB + go);
                cp16(sd + 16384 + so, vhB + go);
                cp16(sd + 24576 + so, vlB + go);
            }
            CP_COMMIT(); CP_WAIT1();
        } else {
            CP_WAIT0();
        }
        __syncthreads();

        const uint32_t sb = smb + (t & 1) * STG;

        // ---- S = Qh*Kh + Qh*Kl + Ql*Kh ----
        float c[8][4];
        #pragma unroll
        for (int i = 0; i < 8; i++)
            #pragma unroll
            for (int j = 0; j < 4; j++) c[i][j] = 0.f;

        #pragma unroll
        for (int kb = 0; kb < 4; kb++) {
            #pragma unroll
            for (int j = 0; j < 4; j++) {
                const int brow = j * 16 + ((mg >> 1) << 3) + mr;
                const int bcol = kb * 32 + ((mg & 1) << 4);
                uint32_t bhr[4], blr[4];
                ldsm_x4(bhr, sb + swzo(brow, bcol));
                ldsm_x4(blr, sb + 8192 + swzo(brow, bcol));
                mma16816(c[2 * j],     qh[kb], bhr[0], bhr[1]);
                mma16816(c[2 * j + 1], qh[kb], bhr[2], bhr[3]);
                mma16816(c[2 * j],     qh[kb], blr[0], blr[1]);
                mma16816(c[2 * j + 1], qh[kb], blr[2], blr[3]);
                mma16816(c[2 * j],     ql[kb], bhr[0], bhr[1]);
                mma16816(c[2 * j + 1], ql[kb], bhr[2], bhr[3]);
            }
        }

        // ---- mask + scaled exp ----
        uint2 w0 = *(const uint2*)(ab0 + t * 2);
        uint2 w1 = *(const uint2*)(ab1 + t * 2);
        uint64_t m0 = (uint64_t)w0.x | ((uint64_t)w0.y << 32);
        uint64_t m1 = (uint64_t)w1.x | ((uint64_t)w1.y << 32);
        #pragma unroll
        for (int nb = 0; nb < 8; nb++) {
            const int cb = nb * 8 + qd * 2;
            #pragma unroll
            for (int qq = 0; qq < 2; qq++) {
                float tv = fmaf(c[nb][qq], K2E, sb0);
                float p = ((m0 >> (cb + qq)) & 1u) ? ex2(tv) : 0.f;
                l0 += p; c[nb][qq] = p;
                tv = fmaf(c[nb][2 + qq], K2E, sb1);
                p = ((m1 >> (cb + qq)) & 1u) ? ex2(tv) : 0.f;
                l1 += p; c[nb][2 + qq] = p;
            }
        }

        // ---- O += Ph*Vh + Ph*Vl + Pl*Vh ----
        #pragma unroll
        for (int kb2 = 0; kb2 < 4; kb2++) {
            const int e = 2 * kb2, od = e + 1;
            uint32_t ph[4], pl[4];
            {
                __half2 h; float2 f; __half2 lw;
                h = __floats2half2_rn(c[e][0], c[e][1]);  f = __half22float2(h);
                lw = __floats2half2_rn(c[e][0] - f.x, c[e][1] - f.y);
                ph[0] = h2bits(h); pl[0] = h2bits(lw);
                h = __floats2half2_rn(c[e][2], c[e][3]);  f = __half22float2(h);
                lw = __floats2half2_rn(c[e][2] - f.x, c[e][3] - f.y);
                ph[1] = h2bits(h); pl[1] = h2bits(lw);
                h = __floats2half2_rn(c[od][0], c[od][1]); f = __half22float2(h);
                lw = __floats2half2_rn(c[od][0] - f.x, c[od][1] - f.y);
                ph[2] = h2bits(h); pl[2] = h2bits(lw);
                h = __floats2half2_rn(c[od][2], c[od][3]); f = __half22float2(h);
                lw = __floats2half2_rn(c[od][2] - f.x, c[od][3] - f.y);
                ph[3] = h2bits(h); pl[3] = h2bits(lw);
            }
            #pragma unroll
            for (int j = 0; j < 4; j++) {
                const int vrow = kb2 * 16 + ((mg & 1) << 3) + mr;
                const int vcol = j * 32 + ((mg >> 1) << 4);
                uint32_t vh4[4], vl4[4];
                ldsm_x4t(vh4, sb + 16384 + swzo(vrow, vcol));
                ldsm_x4t(vl4, sb + 24576 + swzo(vrow, vcol));
                mma16816(o[2 * j],     ph, vh4[0], vh4[1]);
                mma16816(o[2 * j + 1], ph, vh4[2], vh4[3]);
                mma16816(o[2 * j],     ph, vl4[0], vl4[1]);
                mma16816(o[2 * j + 1], ph, vl4[2], vl4[3]);
                mma16816(o[2 * j],     pl, vh4[0], vh4[1]);
                mma16816(o[2 * j + 1], pl, vh4[2], vh4[3]);
            }
        }
        __syncthreads();
    }

    // ---- normalize + store ----
    l0 += __shfl_xor_sync(0xffffffffu, l0, 1);
    l0 += __shfl_xor_sync(0xffffffffu, l0, 2);
    l1 += __shfl_xor_sync(0xffffffffu, l1, 1);
    l1 += __shfl_xor_sync(0xffffffffu, l1, 2);
    const float inv0 = 1.0f / l0;
    const float inv1 = 1.0f / l1;

    const int orow = row0 + wid * 16 + r4;
    float2* op = (float2*)out;
    #pragma unroll
    for (int nb = 0; nb < 8; nb++) {
        const int d = nb * 8 + qd * 2;
        op[(((size_t)bh * N + orow) * DHD + d) >> 1] =
            make_float2(o[nb][0] * inv0, o[nb][1] * inv0);
        op[(((size_t)bh * N + orow + 8) * DHD + d) >> 1] =
            make_float2(o[nb][2] * inv1, o[nb][3] * inv1);
    }
}

// ---------------- launcher ----------------
extern "C" void kernel_launch(void* const* d_in, const int* in_sizes, int n_in,
                              void* d_out, int out_size)
{
    const float* Q   = (const float*)d_in[0];
    const float* K   = (const float*)d_in[1];
    const float* V   = (const float*)d_in[2];
    const int*   adj = (const int*)d_in[3];
    float*       out = (float*)d_out;

    const int N  = (int)(sqrt((double)in_sizes[3]) + 0.5);
    const int BH = in_sizes[0] / (N * DHD);

    pack_adj_kernel<<<(N * N / 4) / 256, 256>>>((const int4*)adj);
    cvt_prepass<<<(BH * N * DHD / 4) / 256, 256>>>(
        (const float4*)Q, (const float4*)K, (const float4*)V, N);

    cudaFuncSetAttribute(gat_hmma2_kernel,
                         cudaFuncAttributeMaxDynamicSharedMemorySize, SMEM_TOTAL);
    dim3 grid(N / BM, BH);
    gat_hmma2_kernel<<<grid, TPB, SMEM_TOTAL>>>(out, N);
}

// round 7
// speedup vs baseline: 4.5230x; 1.2020x over previous
#include <cuda_runtime.h>
#include <cuda_fp16.h>
#include <math.h>
#include <stdint.h>

#define TPB 128
#define BM  64
#define BN  64
#define DHD 64
#define K2E 0.1803368801f   // log2(e)/8

// problem-shape constants (B=4,H=8,N=2048,D=64)
#define BH_MAX 32
#define N_MAX  2048
#define MAXE   (BH_MAX * N_MAX * DHD)

// stage layout (bytes): KH 0, KL 8192, VH 16384, VL 24576; stage stride 32768
#define STG 32768
#define SMEM_TOTAL (2 * STG)

__device__ __align__(16) __half g_qh[MAXE];
__device__ __align__(16) __half g_ql[MAXE];
__device__ __align__(16) __half g_kh[MAXE];
__device__ __align__(16) __half g_kl[MAXE];
__device__ __align__(16) __half g_vh[MAXE];
__device__ __align__(16) __half g_vl[MAXE];
__device__ float    g_qn2[BH_MAX * N_MAX];
__device__ float    g_maxk2[BH_MAX];
__device__ uint32_t g_adjbits[N_MAX * N_MAX / 32];

// ---------------- helpers ----------------
__device__ __forceinline__ uint32_t smem_u32(const void* p) {
    uint32_t a;
    asm("{ .reg .u64 t; cvta.to.shared.u64 t, %1; cvt.u32.u64 %0, t; }" : "=r"(a) : "l"(p));
    return a;
}
__device__ __forceinline__ void cp16(uint32_t dst, const void* src) {
    asm volatile("cp.async.cg.shared.global [%0], [%1], 16;" :: "r"(dst), "l"(src));
}
#define CP_COMMIT() asm volatile("cp.async.commit_group;" ::: "memory")
#define CP_WAIT0()  asm volatile("cp.async.wait_group 0;" ::: "memory")
#define CP_WAIT1()  asm volatile("cp.async.wait_group 1;" ::: "memory")

__device__ __forceinline__ void ldsm_x4(uint32_t* r, uint32_t a) {
    asm volatile("ldmatrix.sync.aligned.m8n8.x4.shared.b16 {%0,%1,%2,%3}, [%4];"
                 : "=r"(r[0]), "=r"(r[1]), "=r"(r[2]), "=r"(r[3]) : "r"(a));
}
__device__ __forceinline__ void ldsm_x4t(uint32_t* r, uint32_t a) {
    asm volatile("ldmatrix.sync.aligned.m8n8.x4.trans.shared.b16 {%0,%1,%2,%3}, [%4];"
                 : "=r"(r[0]), "=r"(r[1]), "=r"(r[2]), "=r"(r[3]) : "r"(a));
}
__device__ __forceinline__ void mma16816(float* c, const uint32_t* a, uint32_t b0, uint32_t b1) {
    asm volatile("mma.sync.aligned.m16n8k16.row.col.f32.f16.f16.f32 "
                 "{%0,%1,%2,%3}, {%4,%5,%6,%7}, {%8,%9}, {%0,%1,%2,%3};"
                 : "+f"(c[0]), "+f"(c[1]), "+f"(c[2]), "+f"(c[3])
                 : "r"(a[0]), "r"(a[1]), "r"(a[2]), "r"(a[3]), "r"(b0), "r"(b1));
}
__device__ __forceinline__ float ex2(float x) {
    float r; asm("ex2.approx.f32 %0, %1;" : "=f"(r) : "f"(x)); return r;
}
__device__ __forceinline__ uint32_t h2bits(__half2 h) { return *(uint32_t*)&h; }
// 128B-row XOR swizzle (conflict-free ldmatrix + cp.async dst)
__device__ __forceinline__ uint32_t swzo(int row, int colb) {
    return (uint32_t)((row * 128 + colb) ^ ((row & 7) << 4));
}

// ---------------- prepass: convert + norms ----------------
__global__ void cvt_prepass(const float4* __restrict__ Q, const float4* __restrict__ K,
                            const float4* __restrict__ V, int N)
{
    __shared__ float skn[16];
    const int idx = blockIdx.x * 256 + threadIdx.x;   // float4 index
    float4 q = Q[idx], k = K[idx], v = V[idx];

    {
        __half2 h0, h1, l0, l1; float2 f0, f1;
        h0 = __floats2half2_rn(q.x, q.y); h1 = __floats2half2_rn(q.z, q.w);
        f0 = __half22float2(h0); f1 = __half22float2(h1);
        l0 = __floats2half2_rn(q.x - f0.x, q.y - f0.y);
        l1 = __floats2half2_rn(q.z - f1.x, q.w - f1.y);
        ((uint2*)g_qh)[idx] = make_uint2(h2bits(h0), h2bits(h1));
        ((uint2*)g_ql)[idx] = make_uint2(h2bits(l0), h2bits(l1));
        h0 = __floats2half2_rn(k.x, k.y); h1 = __floats2half2_rn(k.z, k.w);
        f0 = __half22float2(h0); f1 = __half22float2(h1);
        l0 = __floats2half2_rn(k.x - f0.x, k.y - f0.y);
        l1 = __floats2half2_rn(k.z - f1.x, k.w - f1.y);
        ((uint2*)g_kh)[idx] = make_uint2(h2bits(h0), h2bits(h1));
        ((uint2*)g_kl)[idx] = make_uint2(h2bits(l0), h2bits(l1));
        h0 = __floats2half2_rn(v.x, v.y); h1 = __floats2half2_rn(v.z, v.w);
        f0 = __half22float2(h0); f1 = __half22float2(h1);
        l0 = __floats2half2_rn(v.x - f0.x, v.y - f0.y);
        l1 = __floats2half2_rn(v.z - f1.x, v.w - f1.y);
        ((uint2*)g_vh)[idx] = make_uint2(h2bits(h0), h2bits(h1));
        ((uint2*)g_vl)[idx] = make_uint2(h2bits(l0), h2bits(l1));
    }

    float qn2 = q.x * q.x + q.y * q.y + q.z * q.z + q.w * q.w;
    float kn2 = k.x * k.x + k.y * k.y + k.z * k.z + k.w * k.w;
    #pragma unroll
    for (int o = 8; o; o >>= 1) {
        qn2 += __shfl_xor_sync(0xffffffffu, qn2, o);
        kn2 += __shfl_xor_sync(0xffffffffu, kn2, o);
    }
    if ((threadIdx.x & 15) == 0) {
        g_qn2[idx >> 4] = qn2;
        skn[threadIdx.x >> 4] = kn2;
    }
    __syncthreads();
    if (threadIdx.x == 0) {
        float m = skn[0];
        #pragma unroll
        for (int i = 1; i < 16; i++) m = fmaxf(m, skn[i]);
        int bh = (idx >> 4) / N;
        atomicMax((int*)&g_maxk2[bh], __float_as_int(m));
    }
}

// ---------------- prepass: adjacency bit-pack (2x int4 + shfl gather) ----------------
__global__ void pack_adj_kernel(const int4* __restrict__ adj) {
    const int g = blockIdx.x * 256 + threadIdx.x;   // 8-int group index
    int4 a = adj[2 * g], b = adj[2 * g + 1];
    uint32_t byte = (a.x > 0 ? 1u : 0u)  | (a.y > 0 ? 2u : 0u)
                  | (a.z > 0 ? 4u : 0u)  | (a.w > 0 ? 8u : 0u)
                  | (b.x > 0 ? 16u : 0u) | (b.y > 0 ? 32u : 0u)
                  | (b.z > 0 ? 64u : 0u) | (b.w > 0 ? 128u : 0u);
    uint32_t v = byte << (8 * (threadIdx.x & 3));
    v |= __shfl_xor_sync(0xffffffffu, v, 1);
    v |= __shfl_xor_sync(0xffffffffu, v, 2);
    if ((threadIdx.x & 3) == 0) g_adjbits[g >> 2] = v;
}

// ---------------- main kernel ----------------
__global__ __launch_bounds__(TPB, 3)
void gat_hmma3_kernel(float* __restrict__ out, int N)
{
    extern __shared__ char sm[];
    const uint32_t smb = smem_u32(sm);

    const int tid  = threadIdx.x;
    const int wid  = tid >> 5;
    const int lane = tid & 31;
    const int mg   = lane >> 3;
    const int mr   = lane & 7;
    const int r4   = lane >> 2;
    const int qd   = lane & 3;

    const int bh   = blockIdx.y;
    const int row0 = blockIdx.x * BM;
    const int nT   = N / BN;
    const int adjw = N >> 5;

    // ---- Q fragments: stage QH/QL into buf0, ldmatrix to regs ----
    {
        const char* qhB = (const char*)g_qh + ((size_t)bh * N + row0) * (DHD * 2);
        const char* qlB = (const char*)g_ql + ((size_t)bh * N + row0) * (DHD * 2);
        #pragma unroll
        for (int i = 0; i < 4; i++) {
            int idx = tid + i * TPB;
            int row = idx >> 3, c = idx & 7;
            uint32_t so = swzo(row, c * 16);
            cp16(smb + so,        qhB + row * 128 + c * 16);
            cp16(smb + 8192 + so, qlB + row * 128 + c * 16);
        }
        CP_COMMIT(); CP_WAIT0();
        __syncthreads();
    }
    uint32_t qh[4][4], ql[4][4];
    {
        const int arow = wid * 16 + ((mg & 1) << 3) + mr;
        #pragma unroll
        for (int kb = 0; kb < 4; kb++) {
            const int acol = kb * 32 + ((mg >> 1) << 4);
            ldsm_x4(qh[kb], smb + swzo(arow, acol));
            ldsm_x4(ql[kb], smb + 8192 + swzo(arow, acol));
        }
    }
    __syncthreads();   // buf0 free for tile 0

    // ---- per-row bias + adjacency pointers ----
    const float mk2 = g_maxk2[bh];
    const float qn2a = g_qn2[(size_t)bh * N + row0 + wid * 16 + r4];
    const float qn2b = g_qn2[(size_t)bh * N + row0 + wid * 16 + 8 + r4];
    const float sb0 = 14.0f - sqrtf(qn2a * mk2) * K2E;
    const float sb1 = 14.0f - sqrtf(qn2b * mk2) * K2E;
    const uint32_t* ab0 = g_adjbits + (size_t)(row0 + wid * 16 + r4) * adjw;
    const uint32_t* ab1 = ab0 + (size_t)8 * adjw;

    const char* khB = (const char*)g_kh + (size_t)bh * N * (DHD * 2);
    const char* klB = (const char*)g_kl + (size_t)bh * N * (DHD * 2);
    const char* vhB = (const char*)g_vh + (size_t)bh * N * (DHD * 2);
    const char* vlB = (const char*)g_vl + (size_t)bh * N * (DHD * 2);

    float o[8][4];
    #pragma unroll
    for (int i = 0; i < 8; i++)
        #pragma unroll
        for (int j = 0; j < 4; j++) o[i][j] = 0.f;
    float l0 = 0.f, l1 = 0.f;

    // prefetch tile 0 into stage 0
    {
        #pragma unroll
        for (int i = 0; i < 4; i++) {
            int idx = tid + i * TPB;
            int row = idx >> 3, c = idx & 7;
            uint32_t so = swzo(row, c * 16);
            size_t go = (size_t)row * 128 + c * 16;
            cp16(smb + so,         khB + go);
            cp16(smb + 8192  + so, klB + go);
            cp16(smb + 16384 + so, vhB + go);
            cp16(smb + 24576 + so, vlB + go);
        }
        CP_COMMIT();
    }

    for (int t = 0; t < nT; t++) {
        if (t + 1 < nT) {
            const uint32_t sd = smb + ((t + 1) & 1) * STG;
            const size_t tb = (size_t)(t + 1) * BN * (DHD * 2);
            #pragma unroll
            for (int i = 0; i < 4; i++) {
                int idx = tid + i * TPB;
                int row = idx >> 3, c = idx & 7;
                uint32_t so = swzo(row, c * 16);
                size_t go = tb + (size_t)row * 128 + c * 16;
                cp16(sd + so,         khB + go);
                cp16(sd + 8192  + so, klB + go);
                cp16(sd + 16384 + so, vhB + go);
                cp16(sd + 24576 + so, vlB + go);
            }
            CP_COMMIT(); CP_WAIT1();
        } else {
            CP_WAIT0();
        }
        __syncthreads();

        const uint32_t sb = smb + (t & 1) * STG;

        // ---- S = Qh*Kh + Qh*Kl + Ql*Kh ----
        float c[8][4];
        #pragma unroll
        for (int i = 0; i < 8; i++)
            #pragma unroll
            for (int j = 0; j < 4; j++) c[i][j] = 0.f;

        #pragma unroll
        for (int kb = 0; kb < 4; kb++) {
            #pragma unroll
            for (int j = 0; j < 4; j++) {
                const int brow = j * 16 + ((mg >> 1) << 3) + mr;
                const int bcol = kb * 32 + ((mg & 1) << 4);
                uint32_t bhr[4], blr[4];
                ldsm_x4(bhr, sb + swzo(brow, bcol));
                ldsm_x4(blr, sb + 8192 + swzo(brow, bcol));
                mma16816(c[2 * j],     qh[kb], bhr[0], bhr[1]);
                mma16816(c[2 * j + 1], qh[kb], bhr[2], bhr[3]);
                mma16816(c[2 * j],     qh[kb], blr[0], blr[1]);
                mma16816(c[2 * j + 1], qh[kb], blr[2], blr[3]);
                mma16816(c[2 * j],     ql[kb], bhr[0], bhr[1]);
                mma16816(c[2 * j + 1], ql[kb], bhr[2], bhr[3]);
            }
        }

        // ---- mask + scaled exp ----
        uint2 w0 = *(const uint2*)(ab0 + t * 2);
        uint2 w1 = *(const uint2*)(ab1 + t * 2);
        uint64_t m0 = (uint64_t)w0.x | ((uint64_t)w0.y << 32);
        uint64_t m1 = (uint64_t)w1.x | ((uint64_t)w1.y << 32);
        #pragma unroll
        for (int nb = 0; nb < 8; nb++) {
            const int cb = nb * 8 + qd * 2;
            #pragma unroll
            for (int qq = 0; qq < 2; qq++) {
                float tv = fmaf(c[nb][qq], K2E, sb0);
                float p = ((m0 >> (cb + qq)) & 1u) ? ex2(tv) : 0.f;
                l0 += p; c[nb][qq] = p;
                tv = fmaf(c[nb][2 + qq], K2E, sb1);
                p = ((m1 >> (cb + qq)) & 1u) ? ex2(tv) : 0.f;
                l1 += p; c[nb][2 + qq] = p;
            }
        }

        // ---- O += Ph*Vh + Ph*Vl  (V exact via hi+lo; P single-rounded fp16) ----
        #pragma unroll
        for (int kb2 = 0; kb2 < 4; kb2++) {
            const int e = 2 * kb2, od = e + 1;
            uint32_t ph[4];
            ph[0] = h2bits(__floats2half2_rn(c[e][0],  c[e][1]));
            ph[1] = h2bits(__floats2half2_rn(c[e][2],  c[e][3]));
            ph[2] = h2bits(__floats2half2_rn(c[od][0], c[od][1]));
            ph[3] = h2bits(__floats2half2_rn(c[od][2], c[od][3]));
            #pragma unroll
            for (int j = 0; j < 4; j++) {
                const int vrow = kb2 * 16 + ((mg & 1) << 3) + mr;
                const int vcol = j * 32 + ((mg >> 1) << 4);
                uint32_t vh4[4], vl4[4];
                ldsm_x4t(vh4, sb + 16384 + swzo(vrow, vcol));
                ldsm_x4t(vl4, sb + 24576 + swzo(vrow, vcol));
                mma16816(o[2 * j],     ph, vh4[0], vh4[1]);
                mma16816(o[2 * j + 1], ph, vh4[2], vh4[3]);
                mma16816(o[2 * j],     ph, vl4[0], vl4[1]);
                mma16816(o[2 * j + 1], ph, vl4[2], vl4[3]);
            }
        }
        __syncthreads();
    }

    // ---- normalize + store ----
    l0 += __shfl_xor_sync(0xffffffffu, l0, 1);
    l0 += __shfl_xor_sync(0xffffffffu, l0, 2);
    l1 += __shfl_xor_sync(0xffffffffu, l1, 1);
    l1 += __shfl_xor_sync(0xffffffffu, l1, 2);
    const float inv0 = 1.0f / l0;
    const float inv1 = 1.0f / l1;

    const int orow = row0 + wid * 16 + r4;
    float2* op = (float2*)out;
    #pragma unroll
    for (int nb = 0; nb < 8; nb++) {
        const int d = nb * 8 + qd * 2;
        op[(((size_t)bh * N + orow) * DHD + d) >> 1] =
            make_float2(o[nb][0] * inv0, o[nb][1] * inv0);
        op[(((size_t)bh * N + orow + 8) * DHD + d) >> 1] =
            make_float2(o[nb][2] * inv1, o[nb][3] * inv1);
    }
}

// ---------------- launcher ----------------
extern "C" void kernel_launch(void* const* d_in, const int* in_sizes, int n_in,
                              void* d_out, int out_size)
{
    const float* Q   = (const float*)d_in[0];
    const float* K   = (const float*)d_in[1];
    const float* V   = (const float*)d_in[2];
    const int*   adj = (const int*)d_in[3];
    float*       out = (float*)d_out;

    const int N  = (int)(sqrt((double)in_sizes[3]) + 0.5);
    const int BH = in_sizes[0] / (N * DHD);

    pack_adj_kernel<<<(N * N / 8) / 256, 256>>>((const int4*)adj);
    cvt_prepass<<<(BH * N * DHD / 4) / 256, 256>>>(
        (const float4*)Q, (const float4*)K, (const float4*)V, N);

    cudaFuncSetAttribute(gat_hmma3_kernel,
                         cudaFuncAttributeMaxDynamicSharedMemorySize, SMEM_TOTAL);
    dim3 grid(N / BM, BH);
    gat_hmma3_kernel<<<grid, TPB, SMEM_TOTAL>>>(out, N);
}

// round 8
// speedup vs baseline: 5.6299x; 1.2447x over previous
#include <cuda_runtime.h>
#include <cuda_fp16.h>
#include <math.h>
#include <stdint.h>

#define TPB 128
#define BM  64
#define BN  64
#define DHD 64
#define K2E 0.1803368801f   // log2(e)/8

// problem-shape constants (B=4,H=8,N=2048,D=64)
#define BH_MAX 32
#define N_MAX  2048
#define MAXE   (BH_MAX * N_MAX * DHD)

// stage layout (bytes): KH 0, KL 8192, VH 16384; stage stride 24576
#define STG 24576
#define SMEM_TOTAL (2 * STG)

__device__ __align__(16) __half g_qh[MAXE];
__device__ __align__(16) __half g_ql[MAXE];
__device__ __align__(16) __half g_kh[MAXE];
__device__ __align__(16) __half g_kl[MAXE];
__device__ __align__(16) __half g_vh[MAXE];
__device__ float    g_qn2[BH_MAX * N_MAX];
__device__ float    g_maxk2[BH_MAX];
__device__ uint32_t g_adjbits[N_MAX * N_MAX / 32];

// ---------------- helpers ----------------
__device__ __forceinline__ uint32_t smem_u32(const void* p) {
    uint32_t a;
    asm("{ .reg .u64 t; cvta.to.shared.u64 t, %1; cvt.u32.u64 %0, t; }" : "=r"(a) : "l"(p));
    return a;
}
__device__ __forceinline__ void cp16(uint32_t dst, const void* src) {
    asm volatile("cp.async.cg.shared.global [%0], [%1], 16;" :: "r"(dst), "l"(src));
}
#define CP_COMMIT() asm volatile("cp.async.commit_group;" ::: "memory")
#define CP_WAIT0()  asm volatile("cp.async.wait_group 0;" ::: "memory")
#define CP_WAIT1()  asm volatile("cp.async.wait_group 1;" ::: "memory")

__device__ __forceinline__ void ldsm_x4(uint32_t* r, uint32_t a) {
    asm volatile("ldmatrix.sync.aligned.m8n8.x4.shared.b16 {%0,%1,%2,%3}, [%4];"
                 : "=r"(r[0]), "=r"(r[1]), "=r"(r[2]), "=r"(r[3]) : "r"(a));
}
__device__ __forceinline__ void ldsm_x4t(uint32_t* r, uint32_t a) {
    asm volatile("ldmatrix.sync.aligned.m8n8.x4.trans.shared.b16 {%0,%1,%2,%3}, [%4];"
                 : "=r"(r[0]), "=r"(r[1]), "=r"(r[2]), "=r"(r[3]) : "r"(a));
}
__device__ __forceinline__ void mma16816(float* c, const uint32_t* a, uint32_t b0, uint32_t b1) {
    asm volatile("mma.sync.aligned.m16n8k16.row.col.f32.f16.f16.f32 "
                 "{%0,%1,%2,%3}, {%4,%5,%6,%7}, {%8,%9}, {%0,%1,%2,%3};"
                 : "+f"(c[0]), "+f"(c[1]), "+f"(c[2]), "+f"(c[3])
                 : "r"(a[0]), "r"(a[1]), "r"(a[2]), "r"(a[3]), "r"(b0), "r"(b1));
}
__device__ __forceinline__ float ex2(float x) {
    float r; asm("ex2.approx.f32 %0, %1;" : "=f"(r) : "f"(x)); return r;
}
__device__ __forceinline__ uint32_t h2bits(__half2 h) { return *(uint32_t*)&h; }
// 128B-row XOR swizzle (conflict-free ldmatrix + cp.async dst)
__device__ __forceinline__ uint32_t swzo(int row, int colb) {
    return (uint32_t)((row * 128 + colb) ^ ((row & 7) << 4));
}

// ---------------- prepass: convert + norms ----------------
__global__ void cvt_prepass(const float4* __restrict__ Q, const float4* __restrict__ K,
                            const float4* __restrict__ V, int N)
{
    __shared__ float skn[16];
    const int idx = blockIdx.x * 256 + threadIdx.x;   // float4 index
    float4 q = Q[idx], k = K[idx], v = V[idx];

    {
        __half2 h0, h1, l0, l1; float2 f0, f1;
        h0 = __floats2half2_rn(q.x, q.y); h1 = __floats2half2_rn(q.z, q.w);
        f0 = __half22float2(h0); f1 = __half22float2(h1);
        l0 = __floats2half2_rn(q.x - f0.x, q.y - f0.y);
        l1 = __floats2half2_rn(q.z - f1.x, q.w - f1.y);
        ((uint2*)g_qh)[idx] = make_uint2(h2bits(h0), h2bits(h1));
        ((uint2*)g_ql)[idx] = make_uint2(h2bits(l0), h2bits(l1));
        h0 = __floats2half2_rn(k.x, k.y); h1 = __floats2half2_rn(k.z, k.w);
        f0 = __half22float2(h0); f1 = __half22float2(h1);
        l0 = __floats2half2_rn(k.x - f0.x, k.y - f0.y);
        l1 = __floats2half2_rn(k.z - f1.x, k.w - f1.y);
        ((uint2*)g_kh)[idx] = make_uint2(h2bits(h0), h2bits(h1));
        ((uint2*)g_kl)[idx] = make_uint2(h2bits(l0), h2bits(l1));
        h0 = __floats2half2_rn(v.x, v.y); h1 = __floats2half2_rn(v.z, v.w);
        ((uint2*)g_vh)[idx] = make_uint2(h2bits(h0), h2bits(h1));
    }

    float qn2 = q.x * q.x + q.y * q.y + q.z * q.z + q.w * q.w;
    float kn2 = k.x * k.x + k.y * k.y + k.z * k.z + k.w * k.w;
    #pragma unroll
    for (int o = 8; o; o >>= 1) {
        qn2 += __shfl_xor_sync(0xffffffffu, qn2, o);
        kn2 += __shfl_xor_sync(0xffffffffu, kn2, o);
    }
    if ((threadIdx.x & 15) == 0) {
        g_qn2[idx >> 4] = qn2;
        skn[threadIdx.x >> 4] = kn2;
    }
    __syncthreads();
    if (threadIdx.x == 0) {
        float m = skn[0];
        #pragma unroll
        for (int i = 1; i < 16; i++) m = fmaxf(m, skn[i]);
        int bh = (idx >> 4) / N;
        atomicMax((int*)&g_maxk2[bh], __float_as_int(m));
    }
}

// ---------------- prepass: adjacency bit-pack (8x int4, MLP 8, no shfl) ----------------
__global__ void pack_adj_kernel(const int4* __restrict__ adj) {
    const int g = blockIdx.x * 256 + threadIdx.x;   // one uint32 = 32 ints = 8 int4
    const int4* p = adj + 8 * g;
    int4 a0 = p[0], a1 = p[1], a2 = p[2], a3 = p[3];
    int4 a4 = p[4], a5 = p[5], a6 = p[6], a7 = p[7];
    uint32_t bits = 0;
    #define NIB(A, s) bits |= ((A.x > 0 ? 1u : 0u) | (A.y > 0 ? 2u : 0u) | \
                               (A.z > 0 ? 4u : 0u) | (A.w > 0 ? 8u : 0u)) << (s)
    NIB(a0, 0); NIB(a1, 4); NIB(a2, 8); NIB(a3, 12);
    NIB(a4, 16); NIB(a5, 20); NIB(a6, 24); NIB(a7, 28);
    #undef NIB
    g_adjbits[g] = bits;
}

// ---------------- main kernel ----------------
__global__ __launch_bounds__(TPB, 4)
void gat_hmma4_kernel(float* __restrict__ out, int N)
{
    extern __shared__ char sm[];
    const uint32_t smb = smem_u32(sm);

    const int tid  = threadIdx.x;
    const int wid  = tid >> 5;
    const int lane = tid & 31;
    const int mg   = lane >> 3;
    const int mr   = lane & 7;
    const int r4   = lane >> 2;
    const int qd   = lane & 3;

    const int bh   = blockIdx.y;
    const int row0 = blockIdx.x * BM;
    const int nT   = N / BN;
    const int adjw = N >> 5;

    // ---- Q fragments: stage QH/QL into buf0, ldmatrix to regs ----
    {
        const char* qhB = (const char*)g_qh + ((size_t)bh * N + row0) * (DHD * 2);
        const char* qlB = (const char*)g_ql + ((size_t)bh * N + row0) * (DHD * 2);
        #pragma unroll
        for (int i = 0; i < 4; i++) {
            int idx = tid + i * TPB;
            int row = idx >> 3, c = idx & 7;
            uint32_t so = swzo(row, c * 16);
            cp16(smb + so,        qhB + row * 128 + c * 16);
            cp16(smb + 8192 + so, qlB + row * 128 + c * 16);
        }
        CP_COMMIT(); CP_WAIT0();
        __syncthreads();
    }
    uint32_t qh[4][4], ql[4][4];
    {
        const int arow = wid * 16 + ((mg & 1) << 3) + mr;
        #pragma unroll
        for (int kb = 0; kb < 4; kb++) {
            const int acol = kb * 32 + ((mg >> 1) << 4);
            ldsm_x4(qh[kb], smb + swzo(arow, acol));
            ldsm_x4(ql[kb], smb + 8192 + swzo(arow, acol));
        }
    }
    __syncthreads();   // buf0 free for tile 0

    // ---- per-row bias + adjacency pointers ----
    const float mk2 = g_maxk2[bh];
    const float qn2a = g_qn2[(size_t)bh * N + row0 + wid * 16 + r4];
    const float qn2b = g_qn2[(size_t)bh * N + row0 + wid * 16 + 8 + r4];
    const float sb0 = 14.0f - sqrtf(qn2a * mk2) * K2E;
    const float sb1 = 14.0f - sqrtf(qn2b * mk2) * K2E;
    const uint32_t* ab0 = g_adjbits + (size_t)(row0 + wid * 16 + r4) * adjw;
    const uint32_t* ab1 = ab0 + (size_t)8 * adjw;

    const char* khB = (const char*)g_kh + (size_t)bh * N * (DHD * 2);
    const char* klB = (const char*)g_kl + (size_t)bh * N * (DHD * 2);
    const char* vhB = (const char*)g_vh + (size_t)bh * N * (DHD * 2);

    float o[8][4];
    #pragma unroll
    for (int i = 0; i < 8; i++)
        #pragma unroll
        for (int j = 0; j < 4; j++) o[i][j] = 0.f;
    float l0 = 0.f, l1 = 0.f;

    // prefetch tile 0 into stage 0
    {
        #pragma unroll
        for (int i = 0; i < 4; i++) {
            int idx = tid + i * TPB;
            int row = idx >> 3, c = idx & 7;
            uint32_t so = swzo(row, c * 16);
            size_t go = (size_t)row * 128 + c * 16;
            cp16(smb + so,         khB + go);
            cp16(smb + 8192  + so, klB + go);
            cp16(smb + 16384 + so, vhB + go);
        }
        CP_COMMIT();
    }

    for (int t = 0; t < nT; t++) {
        if (t + 1 < nT) {
            const uint32_t sd = smb + ((t + 1) & 1) * STG;
            const size_t tb = (size_t)(t + 1) * BN * (DHD * 2);
            #pragma unroll
            for (int i = 0; i < 4; i++) {
                int idx = tid + i * TPB;
                int row = idx >> 3, c = idx & 7;
                uint32_t so = swzo(row, c * 16);
                size_t go = tb + (size_t)row * 128 + c * 16;
                cp16(sd + so,         khB + go);
                cp16(sd + 8192  + so, klB + go);
                cp16(sd + 16384 + so, vhB + go);
            }
            CP_COMMIT(); CP_WAIT1();
        } else {
            CP_WAIT0();
        }
        __syncthreads();

        const uint32_t sb = smb + (t & 1) * STG;

        // ---- S = Qh*Kh + Qh*Kl + Ql*Kh ----
        float c[8][4];
        #pragma unroll
        for (int i = 0; i < 8; i++)
            #pragma unroll
            for (int j = 0; j < 4; j++) c[i][j] = 0.f;

        #pragma unroll
        for (int kb = 0; kb < 4; kb++) {
            #pragma unroll
            for (int j = 0; j < 4; j++) {
                const int brow = j * 16 + ((mg >> 1) << 3) + mr;
                const int bcol = kb * 32 + ((mg & 1) << 4);
                uint32_t bhr[4], blr[4];
                ldsm_x4(bhr, sb + swzo(brow, bcol));
                ldsm_x4(blr, sb + 8192 + swzo(brow, bcol));
                mma16816(c[2 * j],     qh[kb], bhr[0], bhr[1]);
                mma16816(c[2 * j + 1], qh[kb], bhr[2], bhr[3]);
                mma16816(c[2 * j],     qh[kb], blr[0], blr[1]);
                mma16816(c[2 * j + 1], qh[kb], blr[2], blr[3]);
                mma16816(c[2 * j],     ql[kb], bhr[0], bhr[1]);
                mma16816(c[2 * j + 1], ql[kb], bhr[2], bhr[3]);
            }
        }

        // ---- mask + scaled exp ----
        uint2 w0 = *(const uint2*)(ab0 + t * 2);
        uint2 w1 = *(const uint2*)(ab1 + t * 2);
        uint64_t m0 = (uint64_t)w0.x | ((uint64_t)w0.y << 32);
        uint64_t m1 = (uint64_t)w1.x | ((uint64_t)w1.y << 32);
        #pragma unroll
        for (int nb = 0; nb < 8; nb++) {
            const int cb = nb * 8 + qd * 2;
            #pragma unroll
            for (int qq = 0; qq < 2; qq++) {
                float tv = fmaf(c[nb][qq], K2E, sb0);
                float p = ((m0 >> (cb + qq)) & 1u) ? ex2(tv) : 0.f;
                l0 += p; c[nb][qq] = p;
                tv = fmaf(c[nb][2 + qq], K2E, sb1);
                p = ((m1 >> (cb + qq)) & 1u) ? ex2(tv) : 0.f;
                l1 += p; c[nb][2 + qq] = p;
            }
        }

        // ---- O += Ph*Vh  (P and V single-rounded fp16) ----
        #pragma unroll
        for (int kb2 = 0; kb2 < 4; kb2++) {
            const int e = 2 * kb2, od = e + 1;
            uint32_t ph[4];
            ph[0] = h2bits(__floats2half2_rn(c[e][0],  c[e][1]));
            ph[1] = h2bits(__floats2half2_rn(c[e][2],  c[e][3]));
            ph[2] = h2bits(__floats2half2_rn(c[od][0], c[od][1]));
            ph[3] = h2bits(__floats2half2_rn(c[od][2], c[od][3]));
            #pragma unroll
            for (int j = 0; j < 4; j++) {
                const int vrow = kb2 * 16 + ((mg & 1) << 3) + mr;
                const int vcol = j * 32 + ((mg >> 1) << 4);
                uint32_t vh4[4];
                ldsm_x4t(vh4, sb + 16384 + swzo(vrow, vcol));
                mma16816(o[2 * j],     ph, vh4[0], vh4[1]);
                mma16816(o[2 * j + 1], ph, vh4[2], vh4[3]);
            }
        }
        __syncthreads();
    }

    // ---- normalize + store ----
    l0 += __shfl_xor_sync(0xffffffffu, l0, 1);
    l0 += __shfl_xor_sync(0xffffffffu, l0, 2);
    l1 += __shfl_xor_sync(0xffffffffu, l1, 1);
    l1 += __shfl_xor_sync(0xffffffffu, l1, 2);
    const float inv0 = 1.0f / l0;
    const float inv1 = 1.0f / l1;

    const int orow = row0 + wid * 16 + r4;
    float2* op = (float2*)out;
    #pragma unroll
    for (int nb = 0; nb < 8; nb++) {
        const int d = nb * 8 + qd * 2;
        op[(((size_t)bh * N + orow) * DHD + d) >> 1] =
            make_float2(o[nb][0] * inv0, o[nb][1] * inv0);
        op[(((size_t)bh * N + orow + 8) * DHD + d) >> 1] =
            make_float2(o[nb][2] * inv1, o[nb][3] * inv1);
    }
}

// ---------------- launcher ----------------
extern "C" void kernel_launch(void* const* d_in, const int* in_sizes, int n_in,
                              void* d_out, int out_size)
{
    const float* Q   = (const float*)d_in[0];
    const float* K   = (const float*)d_in[1];
    const float* V   = (const float*)d_in[2];
    const int*   adj = (const int*)d_in[3];
    float*       out = (float*)d_out;

    const int N  = (int)(sqrt((double)in_sizes[3]) + 0.5);
    const int BH = in_sizes[0] / (N * DHD);

    pack_adj_kernel<<<(N * N / 32) / 256, 256>>>((const int4*)adj);
    cvt_prepass<<<(BH * N * DHD / 4) / 256, 256>>>(
        (const float4*)Q, (const float4*)K, (const float4*)V, N);

    cudaFuncSetAttribute(gat_hmma4_kernel,
                         cudaFuncAttributeMaxDynamicSharedMemorySize, SMEM_TOTAL);
    dim3 grid(N / BM, BH);
    gat_hmma4_kernel<<<grid, TPB, SMEM_TOTAL>>>(out, N);
}

// round 9
// speedup vs baseline: 7.6658x; 1.3616x over previous
#include <cuda_runtime.h>
#include <cuda_fp16.h>
#include <math.h>
#include <stdint.h>

#define TPB 128
#define BM  64
#define BN  64
#define DHD 64
#define K2E 0.1803368801f   // log2(e)/8

// problem-shape constants (B=4,H=8,N=2048,D=64)
#define BH_MAX 32
#define N_MAX  2048
#define MAXE   (BH_MAX * N_MAX * DHD)

// stage layout (bytes): KH 0, VH 8192; stage stride 16384
#define STG 16384
#define SMEM_TOTAL (2 * STG)

__device__ __align__(16) __half g_qh[MAXE];
__device__ __align__(16) __half g_kh[MAXE];
__device__ __align__(16) __half g_vh[MAXE];
__device__ float    g_qn2[BH_MAX * N_MAX];
__device__ float    g_maxk2[BH_MAX];
__device__ uint32_t g_adjbits[N_MAX * N_MAX / 32];

// ---------------- helpers ----------------
__device__ __forceinline__ uint32_t smem_u32(const void* p) {
    uint32_t a;
    asm("{ .reg .u64 t; cvta.to.shared.u64 t, %1; cvt.u32.u64 %0, t; }" : "=r"(a) : "l"(p));
    return a;
}
__device__ __forceinline__ void cp16(uint32_t dst, const void* src) {
    asm volatile("cp.async.cg.shared.global [%0], [%1], 16;" :: "r"(dst), "l"(src));
}
#define CP_COMMIT() asm volatile("cp.async.commit_group;" ::: "memory")
#define CP_WAIT0()  asm volatile("cp.async.wait_group 0;" ::: "memory")
#define CP_WAIT1()  asm volatile("cp.async.wait_group 1;" ::: "memory")

__device__ __forceinline__ void ldsm_x4(uint32_t* r, uint32_t a) {
    asm volatile("ldmatrix.sync.aligned.m8n8.x4.shared.b16 {%0,%1,%2,%3}, [%4];"
                 : "=r"(r[0]), "=r"(r[1]), "=r"(r[2]), "=r"(r[3]) : "r"(a));
}
__device__ __forceinline__ void ldsm_x4t(uint32_t* r, uint32_t a) {
    asm volatile("ldmatrix.sync.aligned.m8n8.x4.trans.shared.b16 {%0,%1,%2,%3}, [%4];"
                 : "=r"(r[0]), "=r"(r[1]), "=r"(r[2]), "=r"(r[3]) : "r"(a));
}
__device__ __forceinline__ void mma16816(float* c, const uint32_t* a, uint32_t b0, uint32_t b1) {
    asm volatile("mma.sync.aligned.m16n8k16.row.col.f32.f16.f16.f32 "
                 "{%0,%1,%2,%3}, {%4,%5,%6,%7}, {%8,%9}, {%0,%1,%2,%3};"
                 : "+f"(c[0]), "+f"(c[1]), "+f"(c[2]), "+f"(c[3])
                 : "r"(a[0]), "r"(a[1]), "r"(a[2]), "r"(a[3]), "r"(b0), "r"(b1));
}
__device__ __forceinline__ float ex2(float x) {
    float r; asm("ex2.approx.f32 %0, %1;" : "=f"(r) : "f"(x)); return r;
}
__device__ __forceinline__ uint32_t h2bits(__half2 h) { return *(uint32_t*)&h; }
// 128B-row XOR swizzle (conflict-free ldmatrix + cp.async dst)
__device__ __forceinline__ uint32_t swzo(int row, int colb) {
    return (uint32_t)((row * 128 + colb) ^ ((row & 7) << 4));
}

// ---------------- prepass: convert + norms ----------------
__global__ void cvt_prepass(const float4* __restrict__ Q, const float4* __restrict__ K,
                            const float4* __restrict__ V, int N)
{
    __shared__ float skn[16];
    const int idx = blockIdx.x * 256 + threadIdx.x;   // float4 index
    float4 q = Q[idx], k = K[idx], v = V[idx];

    ((uint2*)g_qh)[idx] = make_uint2(h2bits(__floats2half2_rn(q.x, q.y)),
                                     h2bits(__floats2half2_rn(q.z, q.w)));
    ((uint2*)g_kh)[idx] = make_uint2(h2bits(__floats2half2_rn(k.x, k.y)),
                                     h2bits(__floats2half2_rn(k.z, k.w)));
    ((uint2*)g_vh)[idx] = make_uint2(h2bits(__floats2half2_rn(v.x, v.y)),
                                     h2bits(__floats2half2_rn(v.z, v.w)));

    float qn2 = q.x * q.x + q.y * q.y + q.z * q.z + q.w * q.w;
    float kn2 = k.x * k.x + k.y * k.y + k.z * k.z + k.w * k.w;
    #pragma unroll
    for (int o = 8; o; o >>= 1) {
        qn2 += __shfl_xor_sync(0xffffffffu, qn2, o);
        kn2 += __shfl_xor_sync(0xffffffffu, kn2, o);
    }
    if ((threadIdx.x & 15) == 0) {
        g_qn2[idx >> 4] = qn2;
        skn[threadIdx.x >> 4] = kn2;
    }
    __syncthreads();
    if (threadIdx.x == 0) {
        float m = skn[0];
        #pragma unroll
        for (int i = 1; i < 16; i++) m = fmaxf(m, skn[i]);
        int bh = (idx >> 4) / N;
        atomicMax((int*)&g_maxk2[bh], __float_as_int(m));
    }
}

// ---------------- prepass: adjacency bit-pack (2x int4 + shfl gather) ----------------
__global__ void pack_adj_kernel(const int4* __restrict__ adj) {
    const int g = blockIdx.x * 256 + threadIdx.x;   // 8-int group index
    int4 a = adj[2 * g], b = adj[2 * g + 1];
    uint32_t byte = (a.x > 0 ? 1u : 0u)  | (a.y > 0 ? 2u : 0u)
                  | (a.z > 0 ? 4u : 0u)  | (a.w > 0 ? 8u : 0u)
                  | (b.x > 0 ? 16u : 0u) | (b.y > 0 ? 32u : 0u)
                  | (b.z > 0 ? 64u : 0u) | (b.w > 0 ? 128u : 0u);
    uint32_t v = byte << (8 * (threadIdx.x & 3));
    v |= __shfl_xor_sync(0xffffffffu, v, 1);
    v |= __shfl_xor_sync(0xffffffffu, v, 2);
    if ((threadIdx.x & 3) == 0) g_adjbits[g >> 2] = v;
}

// ---------------- main kernel ----------------
__global__ __launch_bounds__(TPB, 4)
void gat_hmma5_kernel(float* __restrict__ out, int N)
{
    extern __shared__ char sm[];
    const uint32_t smb = smem_u32(sm);

    const int tid  = threadIdx.x;
    const int wid  = tid >> 5;
    const int lane = tid & 31;
    const int mg   = lane >> 3;
    const int mr   = lane & 7;
    const int r4   = lane >> 2;
    const int qd   = lane & 3;

    const int bh   = blockIdx.y;
    const int row0 = blockIdx.x * BM;
    const int nT   = N / BN;
    const int adjw = N >> 5;

    // ---- Q fragments: stage QH into buf0, ldmatrix to regs ----
    {
        const char* qhB = (const char*)g_qh + ((size_t)bh * N + row0) * (DHD * 2);
        #pragma unroll
        for (int i = 0; i < 4; i++) {
            int idx = tid + i * TPB;
            int row = idx >> 3, c = idx & 7;
            cp16(smb + swzo(row, (c & 7) * 16), qhB + row * 128 + c * 16);
        }
        CP_COMMIT(); CP_WAIT0();
        __syncthreads();
    }
    uint32_t qh[4][4];
    {
        const int arow = wid * 16 + ((mg & 1) << 3) + mr;
        #pragma unroll
        for (int kb = 0; kb < 4; kb++) {
            const int acol = kb * 32 + ((mg >> 1) << 4);
            ldsm_x4(qh[kb], smb + swzo(arow, acol));
        }
    }
    __syncthreads();   // buf0 free for tile 0

    // ---- per-row bias + adjacency pointers ----
    const float mk2 = g_maxk2[bh];
    const float qn2a = g_qn2[(size_t)bh * N + row0 + wid * 16 + r4];
    const float qn2b = g_qn2[(size_t)bh * N + row0 + wid * 16 + 8 + r4];
    const float sb0 = 14.0f - sqrtf(qn2a * mk2) * K2E;
    const float sb1 = 14.0f - sqrtf(qn2b * mk2) * K2E;
    const uint32_t* ab0 = g_adjbits + (size_t)(row0 + wid * 16 + r4) * adjw;
    const uint32_t* ab1 = ab0 + (size_t)8 * adjw;

    const char* khB = (const char*)g_kh + (size_t)bh * N * (DHD * 2);
    const char* vhB = (const char*)g_vh + (size_t)bh * N * (DHD * 2);

    float o[8][4];
    #pragma unroll
    for (int i = 0; i < 8; i++)
        #pragma unroll
        for (int j = 0; j < 4; j++) o[i][j] = 0.f;
    float l0 = 0.f, l1 = 0.f;

    // prefetch tile 0 into stage 0
    {
        #pragma unroll
        for (int i = 0; i < 4; i++) {
            int idx = tid + i * TPB;
            int row = idx >> 3, c = idx & 7;
            uint32_t so = swzo(row, c * 16);
            size_t go = (size_t)row * 128 + c * 16;
            cp16(smb + so,        khB + go);
            cp16(smb + 8192 + so, vhB + go);
        }
        CP_COMMIT();
    }

    for (int t = 0; t < nT; t++) {
        if (t + 1 < nT) {
            const uint32_t sd = smb + ((t + 1) & 1) * STG;
            const size_t tb = (size_t)(t + 1) * BN * (DHD * 2);
            #pragma unroll
            for (int i = 0; i < 4; i++) {
                int idx = tid + i * TPB;
                int row = idx >> 3, c = idx & 7;
                uint32_t so = swzo(row, c * 16);
                size_t go = tb + (size_t)row * 128 + c * 16;
                cp16(sd + so,        khB + go);
                cp16(sd + 8192 + so, vhB + go);
            }
            CP_COMMIT(); CP_WAIT1();
        } else {
            CP_WAIT0();
        }
        __syncthreads();

        const uint32_t sb = smb + (t & 1) * STG;

        // ---- S = Qh*Kh ----
        float c[8][4];
        #pragma unroll
        for (int i = 0; i < 8; i++)
            #pragma unroll
            for (int j = 0; j < 4; j++) c[i][j] = 0.f;

        #pragma unroll
        for (int kb = 0; kb < 4; kb++) {
            #pragma unroll
            for (int j = 0; j < 4; j++) {
                const int brow = j * 16 + ((mg >> 1) << 3) + mr;
                const int bcol = kb * 32 + ((mg & 1) << 4);
                uint32_t bhr[4];
                ldsm_x4(bhr, sb + swzo(brow, bcol));
                mma16816(c[2 * j],     qh[kb], bhr[0], bhr[1]);
                mma16816(c[2 * j + 1], qh[kb], bhr[2], bhr[3]);
            }
        }

        // ---- mask + scaled exp ----
        uint2 w0 = *(const uint2*)(ab0 + t * 2);
        uint2 w1 = *(const uint2*)(ab1 + t * 2);
        uint64_t m0 = (uint64_t)w0.x | ((uint64_t)w0.y << 32);
        uint64_t m1 = (uint64_t)w1.x | ((uint64_t)w1.y << 32);
        #pragma unroll
        for (int nb = 0; nb < 8; nb++) {
            const int cb = nb * 8 + qd * 2;
            #pragma unroll
            for (int qq = 0; qq < 2; qq++) {
                float tv = fmaf(c[nb][qq], K2E, sb0);
                float p = ((m0 >> (cb + qq)) & 1u) ? ex2(tv) : 0.f;
                l0 += p; c[nb][qq] = p;
                tv = fmaf(c[nb][2 + qq], K2E, sb1);
                p = ((m1 >> (cb + qq)) & 1u) ? ex2(tv) : 0.f;
                l1 += p; c[nb][2 + qq] = p;
            }
        }

        // ---- O += Ph*Vh ----
        #pragma unroll
        for (int kb2 = 0; kb2 < 4; kb2++) {
            const int e = 2 * kb2, od = e + 1;
            uint32_t ph[4];
            ph[0] = h2bits(__floats2half2_rn(c[e][0],  c[e][1]));
            ph[1] = h2bits(__floats2half2_rn(c[e][2],  c[e][3]));
            ph[2] = h2bits(__floats2half2_rn(c[od][0], c[od][1]));
            ph[3] = h2bits(__floats2half2_rn(c[od][2], c[od][3]));
            #pragma unroll
            for (int j = 0; j < 4; j++) {
                const int vrow = kb2 * 16 + ((mg & 1) << 3) + mr;
                const int vcol = j * 32 + ((mg >> 1) << 4);
                uint32_t vh4[4];
                ldsm_x4t(vh4, sb + 8192 + swzo(vrow, vcol));
                mma16816(o[2 * j],     ph, vh4[0], vh4[1]);
                mma16816(o[2 * j + 1], ph, vh4[2], vh4[3]);
            }
        }
        __syncthreads();
    }

    // ---- normalize + store ----
    l0 += __shfl_xor_sync(0xffffffffu, l0, 1);
    l0 += __shfl_xor_sync(0xffffffffu, l0, 2);
    l1 += __shfl_xor_sync(0xffffffffu, l1, 1);
    l1 += __shfl_xor_sync(0xffffffffu, l1, 2);
    const float inv0 = 1.0f / l0;
    const float inv1 = 1.0f / l1;

    const int orow = row0 + wid * 16 + r4;
    float2* op = (float2*)out;
    #pragma unroll
    for (int nb = 0; nb < 8; nb++) {
        const int d = nb * 8 + qd * 2;
        op[(((size_t)bh * N + orow) * DHD + d) >> 1] =
            make_float2(o[nb][0] * inv0, o[nb][1] * inv0);
        op[(((size_t)bh * N + orow + 8) * DHD + d) >> 1] =
            make_float2(o[nb][2] * inv1, o[nb][3] * inv1);
    }
}

// ---------------- launcher ----------------
extern "C" void kernel_launch(void* const* d_in, const int* in_sizes, int n_in,
                              void* d_out, int out_size)
{
    const float* Q   = (const float*)d_in[0];
    const float* K   = (const float*)d_in[1];
    const float* V   = (const float*)d_in[2];
    const int*   adj = (const int*)d_in[3];
    float*       out = (float*)d_out;

    const int N  = (int)(sqrt((double)in_sizes[3]) + 0.5);
    const int BH = in_sizes[0] / (N * DHD);

    pack_adj_kernel<<<(N * N / 8) / 256, 256>>>((const int4*)adj);
    cvt_prepass<<<(BH * N * DHD / 4) / 256, 256>>>(
        (const float4*)Q, (const float4*)K, (const float4*)V, N);

    cudaFuncSetAttribute(gat_hmma5_kernel,
                         cudaFuncAttributeMaxDynamicSharedMemorySize, SMEM_TOTAL);
    dim3 grid(N / BM, BH);
    gat_hmma5_kernel<<<grid, TPB, SMEM_TOTAL>>>(out, N);
}

// round 10
// speedup vs baseline: 7.8493x; 1.0239x over previous
#include <cuda_runtime.h>
#include <cuda_fp16.h>
#include <math.h>
#include <stdint.h>

#define TPB 128
#define BM  64
#define BN  64
#define DHD 64
#define K2E 0.1803368801f   // log2(e)/8

// problem-shape constants (B=4,H=8,N=2048,D=64)
#define BH_MAX 32
#define N_MAX  2048
#define MAXE   (BH_MAX * N_MAX * DHD)

// stage layout (bytes): KH 0, VH 8192; stage stride 16384; 3 stages
#define STG 16384
#define SMEM_TOTAL (3 * STG)

__device__ __align__(16) __half g_qh[MAXE];
__device__ __align__(16) __half g_kh[MAXE];
__device__ __align__(16) __half g_vh[MAXE];
__device__ float    g_qn2[BH_MAX * N_MAX];
__device__ float    g_maxk2[BH_MAX];
__device__ uint32_t g_adjbits[N_MAX * N_MAX / 32];

// ---------------- helpers ----------------
__device__ __forceinline__ uint32_t smem_u32(const void* p) {
    uint32_t a;
    asm("{ .reg .u64 t; cvta.to.shared.u64 t, %1; cvt.u32.u64 %0, t; }" : "=r"(a) : "l"(p));
    return a;
}
__device__ __forceinline__ void cp16(uint32_t dst, const void* src) {
    asm volatile("cp.async.cg.shared.global [%0], [%1], 16;" :: "r"(dst), "l"(src));
}
#define CP_COMMIT() asm volatile("cp.async.commit_group;" ::: "memory")
#define CP_WAIT0()  asm volatile("cp.async.wait_group 0;" ::: "memory")
#define CP_WAIT1()  asm volatile("cp.async.wait_group 1;" ::: "memory")

__device__ __forceinline__ void ldsm_x4(uint32_t* r, uint32_t a) {
    asm volatile("ldmatrix.sync.aligned.m8n8.x4.shared.b16 {%0,%1,%2,%3}, [%4];"
                 : "=r"(r[0]), "=r"(r[1]), "=r"(r[2]), "=r"(r[3]) : "r"(a));
}
__device__ __forceinline__ void ldsm_x4t(uint32_t* r, uint32_t a) {
    asm volatile("ldmatrix.sync.aligned.m8n8.x4.trans.shared.b16 {%0,%1,%2,%3}, [%4];"
                 : "=r"(r[0]), "=r"(r[1]), "=r"(r[2]), "=r"(r[3]) : "r"(a));
}
__device__ __forceinline__ void mma16816(float* c, const uint32_t* a, uint32_t b0, uint32_t b1) {
    asm volatile("mma.sync.aligned.m16n8k16.row.col.f32.f16.f16.f32 "
                 "{%0,%1,%2,%3}, {%4,%5,%6,%7}, {%8,%9}, {%0,%1,%2,%3};"
                 : "+f"(c[0]), "+f"(c[1]), "+f"(c[2]), "+f"(c[3])
                 : "r"(a[0]), "r"(a[1]), "r"(a[2]), "r"(a[3]), "r"(b0), "r"(b1));
}
__device__ __forceinline__ float ex2(float x) {
    float r; asm("ex2.approx.f32 %0, %1;" : "=f"(r) : "f"(x)); return r;
}
__device__ __forceinline__ uint32_t h2bits(__half2 h) { return *(uint32_t*)&h; }
// 128B-row XOR swizzle (conflict-free ldmatrix + cp.async dst)
__device__ __forceinline__ uint32_t swzo(int row, int colb) {
    return (uint32_t)((row * 128 + colb) ^ ((row & 7) << 4));
}

// ---------------- merged prepass: adj bit-pack + convert + norms ----------------
// blocks [0, adjB): pack adjacency;  blocks [adjB, adjB+cvtB): convert QKV
__global__ void prepass_kernel(const int4* __restrict__ adj,
                               const float4* __restrict__ Q,
                               const float4* __restrict__ K,
                               const float4* __restrict__ V,
                               int N, int adjB)
{
    if (blockIdx.x < adjB) {
        const int g = blockIdx.x * 256 + threadIdx.x;   // 8-int group index
        int4 a = adj[2 * g], b = adj[2 * g + 1];
        uint32_t byte = (a.x > 0 ? 1u : 0u)  | (a.y > 0 ? 2u : 0u)
                      | (a.z > 0 ? 4u : 0u)  | (a.w > 0 ? 8u : 0u)
                      | (b.x > 0 ? 16u : 0u) | (b.y > 0 ? 32u : 0u)
                      | (b.z > 0 ? 64u : 0u) | (b.w > 0 ? 128u : 0u);
        uint32_t v = byte << (8 * (threadIdx.x & 3));
        v |= __shfl_xor_sync(0xffffffffu, v, 1);
        v |= __shfl_xor_sync(0xffffffffu, v, 2);
        if ((threadIdx.x & 3) == 0) g_adjbits[g >> 2] = v;
        return;
    }
    __shared__ float skn[16];
    const int idx = (blockIdx.x - adjB) * 256 + threadIdx.x;   // float4 index
    float4 q = Q[idx], k = K[idx], v = V[idx];

    ((uint2*)g_qh)[idx] = make_uint2(h2bits(__floats2half2_rn(q.x, q.y)),
                                     h2bits(__floats2half2_rn(q.z, q.w)));
    ((uint2*)g_kh)[idx] = make_uint2(h2bits(__floats2half2_rn(k.x, k.y)),
                                     h2bits(__floats2half2_rn(k.z, k.w)));
    ((uint2*)g_vh)[idx] = make_uint2(h2bits(__floats2half2_rn(v.x, v.y)),
                                     h2bits(__floats2half2_rn(v.z, v.w)));

    float qn2 = q.x * q.x + q.y * q.y + q.z * q.z + q.w * q.w;
    float kn2 = k.x * k.x + k.y * k.y + k.z * k.z + k.w * k.w;
    #pragma unroll
    for (int o = 8; o; o >>= 1) {
        qn2 += __shfl_xor_sync(0xffffffffu, qn2, o);
        kn2 += __shfl_xor_sync(0xffffffffu, kn2, o);
    }
    if ((threadIdx.x & 15) == 0) {
        g_qn2[idx >> 4] = qn2;
        skn[threadIdx.x >> 4] = kn2;
    }
    __syncthreads();
    if (threadIdx.x == 0) {
        float m = skn[0];
        #pragma unroll
        for (int i = 1; i < 16; i++) m = fmaxf(m, skn[i]);
        int bh = (idx >> 4) / N;
        atomicMax((int*)&g_maxk2[bh], __float_as_int(m));
    }
}

// ---------------- main kernel ----------------
__global__ __launch_bounds__(TPB, 4)
void gat_hmma6_kernel(float* __restrict__ out, int N)
{
    extern __shared__ char sm[];
    const uint32_t smb = smem_u32(sm);

    const int tid  = threadIdx.x;
    const int wid  = tid >> 5;
    const int lane = tid & 31;
    const int mg   = lane >> 3;
    const int mr   = lane & 7;
    const int r4   = lane >> 2;
    const int qd   = lane & 3;

    const int bh   = blockIdx.y;
    const int row0 = blockIdx.x * BM;
    const int nT   = N / BN;
    const int adjw = N >> 5;

    // ---- Q fragments: stage QH into buf0, ldmatrix to regs ----
    {
        const char* qhB = (const char*)g_qh + ((size_t)bh * N + row0) * (DHD * 2);
        #pragma unroll
        for (int i = 0; i < 4; i++) {
            int idx = tid + i * TPB;
            int row = idx >> 3, c = idx & 7;
            cp16(smb + swzo(row, c * 16), qhB + row * 128 + c * 16);
        }
        CP_COMMIT(); CP_WAIT0();
        __syncthreads();
    }
    uint32_t qh[4][4];
    {
        const int arow = wid * 16 + ((mg & 1) << 3) + mr;
        #pragma unroll
        for (int kb = 0; kb < 4; kb++) {
            const int acol = kb * 32 + ((mg >> 1) << 4);
            ldsm_x4(qh[kb], smb + swzo(arow, acol));
        }
    }
    __syncthreads();   // buf0 free for tile 0

    // ---- per-row bias + adjacency pointers ----
    const float mk2 = g_maxk2[bh];
    const float qn2a = g_qn2[(size_t)bh * N + row0 + wid * 16 + r4];
    const float qn2b = g_qn2[(size_t)bh * N + row0 + wid * 16 + 8 + r4];
    const float sb0 = 14.0f - sqrtf(qn2a * mk2) * K2E;
    const float sb1 = 14.0f - sqrtf(qn2b * mk2) * K2E;
    const uint32_t* ab0 = g_adjbits + (size_t)(row0 + wid * 16 + r4) * adjw;
    const uint32_t* ab1 = ab0 + (size_t)8 * adjw;

    const char* khB = (const char*)g_kh + (size_t)bh * N * (DHD * 2);
    const char* vhB = (const char*)g_vh + (size_t)bh * N * (DHD * 2);

    float o[8][4];
    #pragma unroll
    for (int i = 0; i < 8; i++)
        #pragma unroll
        for (int j = 0; j < 4; j++) o[i][j] = 0.f;
    float l0a = 0.f, l0b = 0.f, l1a = 0.f, l1b = 0.f;

    // prefetch tile 0 into stage 0
    {
        #pragma unroll
        for (int i = 0; i < 4; i++) {
            int idx = tid + i * TPB;
            int row = idx >> 3, c = idx & 7;
            uint32_t so = swzo(row, c * 16);
            size_t go = (size_t)row * 128 + c * 16;
            cp16(smb + so,        khB + go);
            cp16(smb + 8192 + so, vhB + go);
        }
        CP_COMMIT();
    }

    int cur = 0, nxt = 1;   // rotating stage indices (mod 3)
    for (int t = 0; t < nT; t++) {
        // prefetch t+1 into stage nxt (its last readers finished before sync(t-?) — see ring proof)
        if (t + 1 < nT) {
            const uint32_t sd = smb + nxt * STG;
            const size_t tb = (size_t)(t + 1) * BN * (DHD * 2);
            #pragma unroll
            for (int i = 0; i < 4; i++) {
                int idx = tid + i * TPB;
                int row = idx >> 3, c = idx & 7;
                uint32_t so = swzo(row, c * 16);
                size_t go = tb + (size_t)row * 128 + c * 16;
                cp16(sd + so,        khB + go);
                cp16(sd + 8192 + so, vhB + go);
            }
            CP_COMMIT(); CP_WAIT1();
        } else {
            CP_WAIT0();
        }
        __syncthreads();   // single barrier per tile (3-stage ring)

        // hoisted adjacency loads — latency overlaps the S-MMA phase
        const uint2 w0 = *(const uint2*)(ab0 + t * 2);
        const uint2 w1 = *(const uint2*)(ab1 + t * 2);

        const uint32_t sb = smb + cur * STG;

        // ---- S = Qh*Kh ----
        float c[8][4];
        #pragma unroll
        for (int i = 0; i < 8; i++)
            #pragma unroll
            for (int j = 0; j < 4; j++) c[i][j] = 0.f;

        #pragma unroll
        for (int kb = 0; kb < 4; kb++) {
            #pragma unroll
            for (int j = 0; j < 4; j++) {
                const int brow = j * 16 + ((mg >> 1) << 3) + mr;
                const int bcol = kb * 32 + ((mg & 1) << 4);
                uint32_t bhr[4];
                ldsm_x4(bhr, sb + swzo(brow, bcol));
                mma16816(c[2 * j],     qh[kb], bhr[0], bhr[1]);
                mma16816(c[2 * j + 1], qh[kb], bhr[2], bhr[3]);
            }
        }

        // ---- mask + scaled exp (4 partial l-chains) ----
        const uint64_t m0 = (uint64_t)w0.x | ((uint64_t)w0.y << 32);
        const uint64_t m1 = (uint64_t)w1.x | ((uint64_t)w1.y << 32);
        #pragma unroll
        for (int nb = 0; nb < 8; nb++) {
            const int cb = nb * 8 + qd * 2;
            float tv0 = fmaf(c[nb][0], K2E, sb0);
            float p0 = ((m0 >> cb) & 1u) ? ex2(tv0) : 0.f;
            float tv1 = fmaf(c[nb][1], K2E, sb0);
            float p1 = ((m0 >> (cb + 1)) & 1u) ? ex2(tv1) : 0.f;
            float tv2 = fmaf(c[nb][2], K2E, sb1);
            float p2 = ((m1 >> cb) & 1u) ? ex2(tv2) : 0.f;
            float tv3 = fmaf(c[nb][3], K2E, sb1);
            float p3 = ((m1 >> (cb + 1)) & 1u) ? ex2(tv3) : 0.f;
            l0a += p0; l0b += p1; l1a += p2; l1b += p3;
            c[nb][0] = p0; c[nb][1] = p1; c[nb][2] = p2; c[nb][3] = p3;
        }

        // ---- O += Ph*Vh ----
        #pragma unroll
        for (int kb2 = 0; kb2 < 4; kb2++) {
            const int e = 2 * kb2, od = e + 1;
            uint32_t ph[4];
            ph[0] = h2bits(__floats2half2_rn(c[e][0],  c[e][1]));
            ph[1] = h2bits(__floats2half2_rn(c[e][2],  c[e][3]));
            ph[2] = h2bits(__floats2half2_rn(c[od][0], c[od][1]));
            ph[3] = h2bits(__floats2half2_rn(c[od][2], c[od][3]));
            #pragma unroll
            for (int j = 0; j < 4; j++) {
                const int vrow = kb2 * 16 + ((mg & 1) << 3) + mr;
                const int vcol = j * 32 + ((mg >> 1) << 4);
                uint32_t vh4[4];
                ldsm_x4t(vh4, sb + 8192 + swzo(vrow, vcol));
                mma16816(o[2 * j],     ph, vh4[0], vh4[1]);
                mma16816(o[2 * j + 1], ph, vh4[2], vh4[3]);
            }
        }
        // no trailing sync: 3-stage ring guarantees next prefetch targets a retired stage

        cur = nxt;
        nxt = (nxt == 2) ? 0 : nxt + 1;
    }

    // ---- normalize + store ----
    float l0 = l0a + l0b, l1 = l1a + l1b;
    l0 += __shfl_xor_sync(0xffffffffu, l0, 1);
    l0 += __shfl_xor_sync(0xffffffffu, l0, 2);
    l1 += __shfl_xor_sync(0xffffffffu, l1, 1);
    l1 += __shfl_xor_sync(0xffffffffu, l1, 2);
    const float inv0 = 1.0f / l0;
    const float inv1 = 1.0f / l1;

    const int orow = row0 + wid * 16 + r4;
    float2* op = (float2*)out;
    #pragma unroll
    for (int nb = 0; nb < 8; nb++) {
        const int d = nb * 8 + qd * 2;
        op[(((size_t)bh * N + orow) * DHD + d) >> 1] =
            make_float2(o[nb][0] * inv0, o[nb][1] * inv0);
        op[(((size_t)bh * N + orow + 8) * DHD + d) >> 1] =
            make_float2(o[nb][2] * inv1, o[nb][3] * inv1);
    }
}

// ---------------- launcher ----------------
extern "C" void kernel_launch(void* const* d_in, const int* in_sizes, int n_in,
                              void* d_out, int out_size)
{
    const float* Q   = (const float*)d_in[0];
    const float* K   = (const float*)d_in[1];
    const float* V   = (const float*)d_in[2];
    const int*   adj = (const int*)d_in[3];
    float*       out = (float*)d_out;

    const int N  = (int)(sqrt((double)in_sizes[3]) + 0.5);
    const int BH = in_sizes[0] / (N * DHD);

    const int adjB = (N * N / 8) / 256;
    const int cvtB = (BH * N * DHD / 4) / 256;
    prepass_kernel<<<adjB + cvtB, 256>>>((const int4*)adj, (const float4*)Q,
                                         (const float4*)K, (const float4*)V, N, adjB);

    cudaFuncSetAttribute(gat_hmma6_kernel,
                         cudaFuncAttributeMaxDynamicSharedMemorySize, SMEM_TOTAL);
    dim3 grid(N / BM, BH);
    gat_hmma6_kernel<<<grid, TPB, SMEM_TOTAL>>>(out, N);
}

// round 11
// speedup vs baseline: 10.5590x; 1.3452x over previous
#include <cuda_runtime.h>
#include <cuda_fp16.h>
#include <math.h>
#include <stdint.h>

#define TPB 128
#define BM  64
#define BN  64
#define DHD 64
#define K2E 0.1803368801f   // log2(e)/8

#define BH_MAX 32
#define N_MAX  2048
#define MAXE   (BH_MAX * N_MAX * DHD)

// stage: 128 rows x 128B (rows 0-63 = K, 64-127 = V); 3 stages
#define STG 16384
#define SMEM_TOTAL (3 * STG)

__device__ __align__(16) __half   g_qh[MAXE];
__device__ __align__(16) __half   g_kv[2 * MAXE];          // [bh][t][128 rows][64 halves]
__device__ float    g_qn2[BH_MAX * N_MAX];
__device__ float    g_maxk2[BH_MAX];
__device__ __align__(16) uint32_t g_mask[N_MAX * N_MAX / 2]; // [row][t][qd][nb] AND-words

// ---------------- helpers ----------------
__device__ __forceinline__ uint32_t smem_u32(const void* p) {
    uint32_t a;
    asm("{ .reg .u64 t; cvta.to.shared.u64 t, %1; cvt.u32.u64 %0, t; }" : "=r"(a) : "l"(p));
    return a;
}
__device__ __forceinline__ void cp16(uint32_t dst, const void* src) {
    asm volatile("cp.async.cg.shared.global [%0], [%1], 16;" :: "r"(dst), "l"(src));
}
#define CP_COMMIT() asm volatile("cp.async.commit_group;" ::: "memory")
#define CP_WAIT0()  asm volatile("cp.async.wait_group 0;" ::: "memory")
#define CP_WAIT1()  asm volatile("cp.async.wait_group 1;" ::: "memory")

__device__ __forceinline__ void ldsm_x4(uint32_t* r, uint32_t a) {
    asm volatile("ldmatrix.sync.aligned.m8n8.x4.shared.b16 {%0,%1,%2,%3}, [%4];"
                 : "=r"(r[0]), "=r"(r[1]), "=r"(r[2]), "=r"(r[3]) : "r"(a));
}
__device__ __forceinline__ void ldsm_x4t(uint32_t* r, uint32_t a) {
    asm volatile("ldmatrix.sync.aligned.m8n8.x4.trans.shared.b16 {%0,%1,%2,%3}, [%4];"
                 : "=r"(r[0]), "=r"(r[1]), "=r"(r[2]), "=r"(r[3]) : "r"(a));
}
__device__ __forceinline__ void mma16816(float* c, const uint32_t* a, uint32_t b0, uint32_t b1) {
    asm volatile("mma.sync.aligned.m16n8k16.row.col.f32.f16.f16.f32 "
                 "{%0,%1,%2,%3}, {%4,%5,%6,%7}, {%8,%9}, {%0,%1,%2,%3};"
                 : "+f"(c[0]), "+f"(c[1]), "+f"(c[2]), "+f"(c[3])
                 : "r"(a[0]), "r"(a[1]), "r"(a[2]), "r"(a[3]), "r"(b0), "r"(b1));
}
__device__ __forceinline__ float ex2(float x) {
    float r; asm("ex2.approx.f32 %0, %1;" : "=f"(r) : "f"(x)); return r;
}
__device__ __forceinline__ uint32_t h2bits(__half2 h) { return *(uint32_t*)&h; }
__device__ __forceinline__ uint32_t swzo(int row, int colb) {
    return (uint32_t)((row * 128 + colb) ^ ((row & 7) << 4));
}

// ---------------- merged prepass ----------------
// blocks [0, adjB): expand adjacency to AND-mask words
// blocks [adjB, adjB+cvtB): convert Q/K/V to fp16, write norms
__global__ void prepass_kernel(const int4* __restrict__ adj,
                               const float4* __restrict__ Q,
                               const float4* __restrict__ K,
                               const float4* __restrict__ V,
                               int N, int adjB)
{
    if (blockIdx.x < adjB) {
        const int g   = blockIdx.x * 256 + threadIdx.x;  // covers 32 adj cols of one row
        const int row = g >> 6, seg = g & 63;
        const int t   = seg >> 1, h = seg & 1;
        const int4* bp = adj + (size_t)row * (N >> 2) + t * 16 + h * 8;
        int4 a[8];
        #pragma unroll
        for (int i = 0; i < 8; i++) a[i] = bp[i];
        uint32_t w[4][4];   // [qd][nb-local]
        #pragma unroll
        for (int i = 0; i < 4; i++) {
            int4 lo = a[2 * i], hi = a[2 * i + 1];
            w[0][i] = (lo.x > 0 ? 0xFFFFu : 0u) | (lo.y > 0 ? 0xFFFF0000u : 0u);
            w[1][i] = (lo.z > 0 ? 0xFFFFu : 0u) | (lo.w > 0 ? 0xFFFF0000u : 0u);
            w[2][i] = (hi.x > 0 ? 0xFFFFu : 0u) | (hi.y > 0 ? 0xFFFF0000u : 0u);
            w[3][i] = (hi.z > 0 ? 0xFFFFu : 0u) | (hi.w > 0 ? 0xFFFF0000u : 0u);
        }
        const int nT = N >> 6;
        #pragma unroll
        for (int qd = 0; qd < 4; qd++)
            ((uint4*)g_mask)[(((size_t)row * nT + t) * 4 + qd) * 2 + h] =
                make_uint4(w[qd][0], w[qd][1], w[qd][2], w[qd][3]);
        return;
    }
    __shared__ float skn[16];
    const int idx = (blockIdx.x - adjB) * 256 + threadIdx.x;   // float4 index
    float4 q = Q[idx], k = K[idx], v = V[idx];

    ((uint2*)g_qh)[idx] = make_uint2(h2bits(__floats2half2_rn(q.x, q.y)),
                                     h2bits(__floats2half2_rn(q.z, q.w)));
    const int rl  = idx >> 4;
    const int bh  = rl / N;
    const int row = rl - bh * N;
    const int t   = row >> 6, r = row & 63, c4 = idx & 15;
    const size_t u2 = ((size_t)(bh * (N >> 6) + t) * 128 + r) * 16 + c4;
    ((uint2*)g_kv)[u2]        = make_uint2(h2bits(__floats2half2_rn(k.x, k.y)),
                                           h2bits(__floats2half2_rn(k.z, k.w)));
    ((uint2*)g_kv)[u2 + 1024] = make_uint2(h2bits(__floats2half2_rn(v.x, v.y)),
                                           h2bits(__floats2half2_rn(v.z, v.w)));

    float qn2 = q.x * q.x + q.y * q.y + q.z * q.z + q.w * q.w;
    float kn2 = k.x * k.x + k.y * k.y + k.z * k.z + k.w * k.w;
    #pragma unroll
    for (int o = 8; o; o >>= 1) {
        qn2 += __shfl_xor_sync(0xffffffffu, qn2, o);
        kn2 += __shfl_xor_sync(0xffffffffu, kn2, o);
    }
    if ((threadIdx.x & 15) == 0) {
        g_qn2[idx >> 4] = qn2;
        skn[threadIdx.x >> 4] = kn2;
    }
    __syncthreads();
    if (threadIdx.x == 0) {
        float m = skn[0];
        #pragma unroll
        for (int i = 1; i < 16; i++) m = fmaxf(m, skn[i]);
        atomicMax((int*)&g_maxk2[bh], __float_as_int(m));
    }
}

// ---------------- main kernel ----------------
__global__ __launch_bounds__(TPB, 4)
void gat_hmma7_kernel(float* __restrict__ out, int N)
{
    extern __shared__ char sm[];
    const uint32_t smb = smem_u32(sm);

    const int tid  = threadIdx.x;
    const int wid  = tid >> 5;
    const int lane = tid & 31;
    const int mg   = lane >> 3;
    const int mr   = lane & 7;
    const int r4   = lane >> 2;
    const int qd   = lane & 3;

    const int bh   = blockIdx.y;
    const int row0 = blockIdx.x * BM;
    const int nT   = N / BN;

    // ---- Q fragments via stage0 ----
    {
        const char* qhB = (const char*)g_qh + ((size_t)bh * N + row0) * (DHD * 2);
        #pragma unroll
        for (int i = 0; i < 4; i++) {
            int idx = tid + i * TPB;
            int row = idx >> 3, c = idx & 7;
            cp16(smb + swzo(row, c * 16), qhB + row * 128 + c * 16);
        }
        CP_COMMIT(); CP_WAIT0();
        __syncthreads();
    }
    uint32_t qh[4][4];
    {
        const int arow = wid * 16 + ((mg & 1) << 3) + mr;
        #pragma unroll
        for (int kb = 0; kb < 4; kb++)
            ldsm_x4(qh[kb], smb + swzo(arow, kb * 32 + ((mg >> 1) << 4)));
    }
    __syncthreads();

    // ---- per-row bias, mask pointers, ones fragment ----
    const float mk2 = g_maxk2[bh];
    const int rowa = row0 + wid * 16 + r4;
    const float sb0 = 14.0f - sqrtf(g_qn2[(size_t)bh * N + rowa] * mk2) * K2E;
    const float sb1 = 14.0f - sqrtf(g_qn2[(size_t)bh * N + rowa + 8] * mk2) * K2E;
    const uint32_t* mpA = g_mask + (size_t)rowa * nT * 32 + qd * 8;
    const uint32_t* mpB = mpA + (size_t)8 * nT * 32;
    const uint32_t bo = (lane < 4) ? 0x3C003C00u : 0u;   // ones column B-fragment

    // ---- hoisted ldsm addresses (swizzle term is thread-constant: row&7 == mr) ----
    const uint32_t mrx = (uint32_t)(mr << 4);
    uint32_t addrS[4], addrV[4];
    {
        uint32_t bS = smb + (uint32_t)((((mg >> 1) << 3) + mr) * 128);
        uint32_t bV = smb + 8192 + (uint32_t)((((mg & 1) << 3) + mr) * 128);
        #pragma unroll
        for (int k = 0; k < 4; k++) {
            addrS[k] = bS + ((uint32_t)(k * 32 + ((mg & 1) << 4)) ^ mrx);
            addrV[k] = bV + ((uint32_t)(k * 32 + ((mg >> 1) << 4)) ^ mrx);
        }
    }

    // ---- cp.async bases (merged KV: one src pointer, imm offsets) ----
    const uint32_t so0 = (uint32_t)((tid >> 3) * 128 + (((tid & 7) * 16) ^ (((tid >> 3) & 7) << 4)));
    const char* kvSrc = (const char*)g_kv + (size_t)bh * N * 256 + (tid >> 3) * 128 + (tid & 7) * 16;
    uint32_t cpDst = smb + STG + so0;
    int cpStage = 1;

    float o[8][4];
    #pragma unroll
    for (int i = 0; i < 8; i++)
        #pragma unroll
        for (int j = 0; j < 4; j++) o[i][j] = 0.f;
    float lfrag[4] = {0.f, 0.f, 0.f, 0.f};

    // prefetch tile 0 -> stage 0
    #pragma unroll
    for (int i = 0; i < 8; i++) cp16(smb + so0 + i * 2048, kvSrc + i * 2048);
    CP_COMMIT();
    kvSrc += 16384;

    int st = 0;
    for (int t = 0; t < nT; t++) {
        if (t + 1 < nT) {
            #pragma unroll
            for (int i = 0; i < 8; i++) cp16(cpDst + i * 2048, kvSrc + i * 2048);
            CP_COMMIT(); CP_WAIT1();
            kvSrc += 16384;
            int d2 = (cpStage == 2) ? -2 * STG : STG;
            cpStage = (cpStage == 2) ? 0 : cpStage + 1;
            cpDst += d2;
        } else {
            CP_WAIT0();
        }
        __syncthreads();   // single barrier per tile (3-stage ring)

        // hoisted mask loads (L2) — latency covered by S-MMA phase
        const uint4 mq0 = *(const uint4*)(mpA);
        const uint4 mq1 = *(const uint4*)(mpA + 4);
        const uint4 mq2 = *(const uint4*)(mpB);
        const uint4 mq3 = *(const uint4*)(mpB + 4);
        mpA += 32; mpB += 32;

        // ---- S = Qh*Kh ----
        float c[8][4];
        #pragma unroll
        for (int i = 0; i < 8; i++)
            #pragma unroll
            for (int j = 0; j < 4; j++) c[i][j] = 0.f;

        #pragma unroll
        for (int kb = 0; kb < 4; kb++) {
            #pragma unroll
            for (int j = 0; j < 4; j++) {
                uint32_t bhr[4];
                ldsm_x4(bhr, addrS[kb] + j * 2048);
                mma16816(c[2 * j],     qh[kb], bhr[0], bhr[1]);
                mma16816(c[2 * j + 1], qh[kb], bhr[2], bhr[3]);
            }
        }

        // ---- exp (no per-element masking — mask applied by AND below) ----
        #pragma unroll
        for (int nb = 0; nb < 8; nb++) {
            c[nb][0] = ex2(fmaf(c[nb][0], K2E, sb0));
            c[nb][1] = ex2(fmaf(c[nb][1], K2E, sb0));
            c[nb][2] = ex2(fmaf(c[nb][2], K2E, sb1));
            c[nb][3] = ex2(fmaf(c[nb][3], K2E, sb1));
        }

        const uint32_t mwA[8] = {mq0.x, mq0.y, mq0.z, mq0.w, mq1.x, mq1.y, mq1.z, mq1.w};
        const uint32_t mwB[8] = {mq2.x, mq2.y, mq2.z, mq2.w, mq3.x, mq3.y, mq3.z, mq3.w};

        // ---- O += Ph*Vh, l += Ph*ones (masking via AND on packed fp16) ----
        #pragma unroll
        for (int kb2 = 0; kb2 < 4; kb2++) {
            const int e = 2 * kb2, od = e + 1;
            uint32_t ph[4];
            ph[0] = h2bits(__floats2half2_rn(c[e][0],  c[e][1]))  & mwA[e];
            ph[1] = h2bits(__floats2half2_rn(c[e][2],  c[e][3]))  & mwB[e];
            ph[2] = h2bits(__floats2half2_rn(c[od][0], c[od][1])) & mwA[od];
            ph[3] = h2bits(__floats2half2_rn(c[od][2], c[od][3])) & mwB[od];
            #pragma unroll
            for (int j = 0; j < 4; j++) {
                uint32_t vh4[4];
                ldsm_x4t(vh4, addrV[j] + kb2 * 2048);
                mma16816(o[2 * j],     ph, vh4[0], vh4[1]);
                mma16816(o[2 * j + 1], ph, vh4[2], vh4[3]);
            }
            mma16816(lfrag, ph, bo, bo);
        }

        // rotate stage bases
        int d = (st == 2) ? -2 * STG : STG;
        st = (st == 2) ? 0 : st + 1;
        #pragma unroll
        for (int k = 0; k < 4; k++) { addrS[k] += d; addrV[k] += d; }
    }

    // ---- normalize + store (l lives in col 0 -> lanes with qd==0) ----
    float l0 = __shfl_sync(0xffffffffu, lfrag[0], lane & 28);
    float l1 = __shfl_sync(0xffffffffu, lfrag[2], lane & 28);
    const float inv0 = 1.0f / l0;
    const float inv1 = 1.0f / l1;

    const int orow = row0 + wid * 16 + r4;
    float2* op = (float2*)out;
    #pragma unroll
    for (int nb = 0; nb < 8; nb++) {
        const int d = nb * 8 + qd * 2;
        op[(((size_t)bh * N + orow) * DHD + d) >> 1] =
            make_float2(o[nb][0] * inv0, o[nb][1] * inv0);
        op[(((size_t)bh * N + orow + 8) * DHD + d) >> 1] =
            make_float2(o[nb][2] * inv1, o[nb][3] * inv1);
    }
}

// ---------------- launcher ----------------
extern "C" void kernel_launch(void* const* d_in, const int* in_sizes, int n_in,
                              void* d_out, int out_size)
{
    const float* Q   = (const float*)d_in[0];
    const float* K   = (const float*)d_in[1];
    const float* V   = (const float*)d_in[2];
    const int*   adj = (const int*)d_in[3];
    float*       out = (float*)d_out;

    const int N  = (int)(sqrt((double)in_sizes[3]) + 0.5);
    const int BH = in_sizes[0] / (N * DHD);

    const int adjB = (N * N / 32) / 256;
    const int cvtB = (BH * N * DHD / 4) / 256;
    prepass_kernel<<<adjB + cvtB, 256>>>((const int4*)adj, (const float4*)Q,
                                         (const float4*)K, (const float4*)V, N, adjB);

    cudaFuncSetAttribute(gat_hmma7_kernel,
                         cudaFuncAttributeMaxDynamicSharedMemorySize, SMEM_TOTAL);
    dim3 grid(N / BM, BH);
    gat_hmma7_kernel<<<grid, TPB, SMEM_TOTAL>>>(out, N);
}